// round 10
// baseline (speedup 1.0000x reference)
#include <cuda_runtime.h>
#include <cuda_bf16.h>
#include <math.h>
#include <stdint.h>

// Problem constants
#define BATCH 16
#define SEQ   1024
#define DIM   1024
#define MTOT  (BATCH*SEQ)            // 16384
#define MS    ((size_t)MTOT*DIM)     // 16777216
#define SD    ((size_t)SEQ*DIM)      // per-batch stride
#define WS    ((size_t)DIM*DIM)

// bf16 hi/lo planes (device globals; cudaMalloc forbidden)
__device__ __nv_bfloat16 g_xhi[6*MS], g_xlo[6*MS];
__device__ __nv_bfloat16 g_whi[6*WS], g_wlo[6*WS];
// proj planes, slots: 0 qr, 1 qi, 2 krT, 3 ki, 4 vrT, 5 viT
__device__ __nv_bfloat16 g_phi[6*MS], g_plo[6*MS];
// temp (untransposed) planes for kr, vr, vi
__device__ __nv_bfloat16 g_thi[3*MS], g_tlo[3*MS];
__device__ __nv_bfloat16 g_ahi[MS],  g_alo[MS];
__device__ float g_scores[(size_t)BATCH*SEQ*SEQ];

// ---------------------------------------------------------------------------
// helpers
// ---------------------------------------------------------------------------
__device__ __forceinline__ uint32_t smem_u32(const void* p) {
    uint32_t r;
    asm("{ .reg .u64 t; cvta.to.shared.u64 t, %1; cvt.u32.u64 %0, t; }"
        : "=r"(r) : "l"(p));
    return r;
}

__device__ __forceinline__ void cp16(uint32_t d, const void* s) {
    asm volatile("cp.async.cg.shared.global [%0], [%1], 16;" :: "r"(d), "l"(s));
}

__device__ __forceinline__ void ldmx4(uint32_t& r0, uint32_t& r1,
                                      uint32_t& r2, uint32_t& r3, uint32_t a) {
    asm volatile("ldmatrix.sync.aligned.m8n8.x4.shared.b16 {%0,%1,%2,%3}, [%4];"
                 : "=r"(r0), "=r"(r1), "=r"(r2), "=r"(r3) : "r"(a));
}

__device__ __forceinline__ void mma16816(float* c, const uint32_t* a,
                                         const uint32_t* b) {
    asm volatile(
        "mma.sync.aligned.m16n8k16.row.col.f32.bf16.bf16.f32 "
        "{%0,%1,%2,%3}, {%4,%5,%6,%7}, {%8,%9}, {%0,%1,%2,%3};"
        : "+f"(c[0]), "+f"(c[1]), "+f"(c[2]), "+f"(c[3])
        : "r"(a[0]), "r"(a[1]), "r"(a[2]), "r"(a[3]), "r"(b[0]), "r"(b[1]));
}

__device__ __forceinline__ void fsplit(float x, __nv_bfloat16& h, float& l) {
    h = __float2bfloat16(x);
    l = x - __bfloat162float(h);
}

// ---------------------------------------------------------------------------
// fp32 -> (hi, lo) bf16 planes, elementwise
// ---------------------------------------------------------------------------
__global__ __launch_bounds__(256)
void conv_split(const float4* __restrict__ in, __nv_bfloat162* __restrict__ hi,
                __nv_bfloat162* __restrict__ lo, size_t n4)
{
    size_t i = (size_t)blockIdx.x * 256 + threadIdx.x;
    if (i >= n4) return;
    float4 v = in[i];
    __nv_bfloat16 h0, h1, h2, h3; float l0, l1, l2, l3;
    fsplit(v.x, h0, l0); fsplit(v.y, h1, l1);
    fsplit(v.z, h2, l2); fsplit(v.w, h3, l3);
    hi[2*i]   = __halves2bfloat162(h0, h1);
    hi[2*i+1] = __halves2bfloat162(h2, h3);
    lo[2*i]   = __halves2bfloat162(__float2bfloat16(l0), __float2bfloat16(l1));
    lo[2*i+1] = __halves2bfloat162(__float2bfloat16(l2), __float2bfloat16(l3));
}

// ---------------------------------------------------------------------------
// Coalesced per-batch 1024x1024 bf16 transpose (64x64 smem tile, padded).
// ---------------------------------------------------------------------------
__global__ __launch_bounds__(256)
void transpose_bf16(const __nv_bfloat16* __restrict__ src,
                    __nv_bfloat16* __restrict__ dst)
{
    __shared__ __nv_bfloat16 t[64][66];
    const size_t bz = blockIdx.z;
    const __nv_bfloat16* s = src + bz * SD;
    __nv_bfloat16* d = dst + bz * SD;

    const int x = blockIdx.x * 64 + threadIdx.x * 2;
    const int y = blockIdx.y * 64 + threadIdx.y;
    #pragma unroll
    for (int j = 0; j < 64; j += 8) {
        __nv_bfloat162 v = *(const __nv_bfloat162*)(s + (size_t)(y + j) * 1024 + x);
        t[threadIdx.y + j][threadIdx.x * 2]     = v.x;
        t[threadIdx.y + j][threadIdx.x * 2 + 1] = v.y;
    }
    __syncthreads();
    const int xo = blockIdx.y * 64 + threadIdx.x * 2;
    const int yo = blockIdx.x * 64 + threadIdx.y;
    #pragma unroll
    for (int j = 0; j < 64; j += 8) {
        __nv_bfloat162 v = __halves2bfloat162(
            t[threadIdx.x * 2][threadIdx.y + j],
            t[threadIdx.x * 2 + 1][threadIdx.y + j]);
        *(__nv_bfloat162*)(d + (size_t)(yo + j) * 1024 + xo) = v;
    }
}

// ---------------------------------------------------------------------------
// Split-bf16 HMMA GEMM (3-stage cp.async ring).
// C[m,n] = sum_seg Aseg[m,:] . Bseg[n,:]  (row-major, ld=1024, K=1024/seg)
// Tile 256x128, 8 warps (4x2), warp tile 64x64, mma m16n8k16.
// Epilogues: 0 = fp32*alpha, 1 = +bias -> split hi/lo bf16 planes.
// ---------------------------------------------------------------------------
#define OPA   20480               // 256 rows * 80B
#define OPB   10240               // 128 rows * 80B
#define STAGE (OPA + OPB)         // 30720
#define NSTAGE 3
#define GSMEM (NSTAGE*STAGE)      // 92160

struct SegPtrs { const __nv_bfloat16* a[6]; const __nv_bfloat16* b[6]; };

template<int EPI>
__global__ __launch_bounds__(256, 1)
void tc_gemm(SegPtrs segs, int nseg, size_t sA, size_t sB,
             float* __restrict__ Cf, size_t sC, float alpha,
             const float* __restrict__ bias,
             __nv_bfloat16* __restrict__ hiP, __nv_bfloat16* __restrict__ loP)
{
    extern __shared__ __align__(128) char sm[];
    __shared__ const __nv_bfloat16* sAp[6];
    __shared__ const __nv_bfloat16* sBp[6];

    const int tid = threadIdx.x;
    const int m0 = blockIdx.y * 256;
    const int n0 = blockIdx.x * 128;
    const size_t bz = blockIdx.z;

    if (tid < 6 && tid < nseg) {
        sAp[tid] = segs.a[tid] + bz * sA + (size_t)m0 * 1024;
        sBp[tid] = segs.b[tid] + bz * sB + (size_t)n0 * 1024;
    }
    __syncthreads();

    const uint32_t smb = smem_u32(sm);
    const int r0 = tid >> 2, c0 = tid & 3;    // 64 rows x 4 col-segs
    const int NIT = nseg * 32;

    auto issue = [&](int it) {
        const int seg = it >> 5, kc = it & 31;
        const uint32_t st = smb + (uint32_t)(it % NSTAGE) * STAGE;
        const __nv_bfloat16* ga = sAp[seg] + kc * 32;
        const __nv_bfloat16* gb = sBp[seg] + kc * 32;
        #pragma unroll
        for (int q = 0; q < 4; q++)
            cp16(st + (r0 + q * 64) * 80 + c0 * 16,
                 ga + (size_t)(r0 + q * 64) * 1024 + c0 * 8);
        #pragma unroll
        for (int q = 0; q < 2; q++)
            cp16(st + OPA + (r0 + q * 64) * 80 + c0 * 16,
                 gb + (size_t)(r0 + q * 64) * 1024 + c0 * 8);
    };

    float acc[4][8][4];
    #pragma unroll
    for (int i = 0; i < 4; i++)
        #pragma unroll
        for (int j = 0; j < 8; j++)
            #pragma unroll
            for (int k = 0; k < 4; k++) acc[i][j][k] = 0.f;

    const int lane = tid & 31, w = tid >> 5;
    const int wm = (w >> 1) * 64;     // warp M offset: 0,64,128,192
    const int wn = (w & 1) * 64;      // warp N offset: 0,64
    const uint32_t lmo = (uint32_t)((lane & 15) * 80 + (lane >> 4) * 16);

    issue(0);
    asm volatile("cp.async.commit_group;" ::: "memory");
    issue(1);
    asm volatile("cp.async.commit_group;" ::: "memory");

    for (int it = 0; it < NIT; ++it) {
        asm volatile("cp.async.wait_group 1;" ::: "memory");
        __syncthreads();
        if (it + 2 < NIT) issue(it + 2);
        asm volatile("cp.async.commit_group;" ::: "memory");

        const uint32_t stg = smb + (uint32_t)(it % NSTAGE) * STAGE;
        const uint32_t sa = stg + wm * 80 + lmo;
        const uint32_t sb = stg + OPA + wn * 80 + lmo;

        #pragma unroll
        for (int ks = 0; ks < 2; ks++) {
            uint32_t Af[4][4], Bf[8][2];
            #pragma unroll
            for (int mt = 0; mt < 4; mt++)
                ldmx4(Af[mt][0], Af[mt][1], Af[mt][2], Af[mt][3],
                      sa + mt * 1280 + ks * 32);
            #pragma unroll
            for (int q = 0; q < 4; q++) {
                uint32_t t0, t1, t2, t3;
                ldmx4(t0, t1, t2, t3, sb + q * 1280 + ks * 32);
                Bf[2*q][0] = t0; Bf[2*q][1] = t2;
                Bf[2*q+1][0] = t1; Bf[2*q+1][1] = t3;
            }
            #pragma unroll
            for (int mt = 0; mt < 4; mt++)
                #pragma unroll
                for (int nt = 0; nt < 8; nt++)
                    mma16816(acc[mt][nt], Af[mt], Bf[nt]);
        }
    }

    // Epilogue. Frag: g=lane>>2, t4=lane&3: c0,c1 -> (row g, cols 2t4,2t4+1),
    // c2,c3 -> (row g+8, same cols).
    const int g = lane >> 2, t4 = lane & 3;
    #pragma unroll
    for (int mt = 0; mt < 4; mt++) {
        #pragma unroll
        for (int nt = 0; nt < 8; nt++) {
            const int rowA = m0 + wm + mt * 16 + g;
            const int rowB = rowA + 8;
            const int col  = n0 + wn + nt * 8 + 2 * t4;
            float c0 = acc[mt][nt][0], c1 = acc[mt][nt][1];
            float c2 = acc[mt][nt][2], c3 = acc[mt][nt][3];
            if (EPI == 0) {
                float2 v0 = make_float2(c0 * alpha, c1 * alpha);
                float2 v1 = make_float2(c2 * alpha, c3 * alpha);
                *(float2*)(Cf + bz * sC + (size_t)rowA * 1024 + col) = v0;
                *(float2*)(Cf + bz * sC + (size_t)rowB * 1024 + col) = v1;
            } else {
                const float b0v = bias[col], b1v = bias[col + 1];
                const float v0 = c0 + b0v, v1 = c1 + b1v;
                const float v2 = c2 + b0v, v3 = c3 + b1v;
                __nv_bfloat16 h0, h1, h2, h3; float l0, l1, l2, l3;
                fsplit(v0, h0, l0); fsplit(v1, h1, l1);
                fsplit(v2, h2, l2); fsplit(v3, h3, l3);
                *(__nv_bfloat162*)(hiP + (size_t)rowA * 1024 + col) =
                    __halves2bfloat162(h0, h1);
                *(__nv_bfloat162*)(hiP + (size_t)rowB * 1024 + col) =
                    __halves2bfloat162(h2, h3);
                *(__nv_bfloat162*)(loP + (size_t)rowA * 1024 + col) =
                    __halves2bfloat162(__float2bfloat16(l0), __float2bfloat16(l1));
                *(__nv_bfloat162*)(loP + (size_t)rowB * 1024 + col) =
                    __halves2bfloat162(__float2bfloat16(l2), __float2bfloat16(l3));
            }
        }
    }
}

// ---------------------------------------------------------------------------
// Row softmax over 1024, writes attn hi/lo bf16 planes.
// ---------------------------------------------------------------------------
__global__ __launch_bounds__(256)
void softmax_split(const float* __restrict__ s, __nv_bfloat16* __restrict__ hi,
                   __nv_bfloat16* __restrict__ lo)
{
    const size_t row = blockIdx.x;
    const float4* p = (const float4*)(s + row * 1024);
    const int tid = threadIdx.x;

    float4 v = p[tid];
    float m = fmaxf(fmaxf(v.x, v.y), fmaxf(v.z, v.w));
    #pragma unroll
    for (int o = 16; o > 0; o >>= 1)
        m = fmaxf(m, __shfl_xor_sync(0xffffffffu, m, o));

    __shared__ float red[8];
    __shared__ float fin[2];
    if ((tid & 31) == 0) red[tid >> 5] = m;
    __syncthreads();
    if (tid < 32) {
        float t = (tid < 8) ? red[tid] : -3.4e38f;
        #pragma unroll
        for (int o = 4; o > 0; o >>= 1)
            t = fmaxf(t, __shfl_xor_sync(0xffffffffu, t, o));
        if (tid == 0) fin[0] = t;
    }
    __syncthreads();
    m = fin[0];

    v.x = expf(v.x - m); v.y = expf(v.y - m);
    v.z = expf(v.z - m); v.w = expf(v.w - m);
    float sum = v.x + v.y + v.z + v.w;
    #pragma unroll
    for (int o = 16; o > 0; o >>= 1)
        sum += __shfl_xor_sync(0xffffffffu, sum, o);
    if ((tid & 31) == 0) red[tid >> 5] = sum;
    __syncthreads();
    if (tid < 32) {
        float t = (tid < 8) ? red[tid] : 0.f;
        #pragma unroll
        for (int o = 4; o > 0; o >>= 1)
            t += __shfl_xor_sync(0xffffffffu, t, o);
        if (tid == 0) fin[1] = t;
    }
    __syncthreads();
    const float inv = 1.0f / fin[1];
    v.x *= inv; v.y *= inv; v.z *= inv; v.w *= inv;

    __nv_bfloat16 h0, h1, h2, h3; float l0, l1, l2, l3;
    fsplit(v.x, h0, l0); fsplit(v.y, h1, l1);
    fsplit(v.z, h2, l2); fsplit(v.w, h3, l3);
    __nv_bfloat162* ph = (__nv_bfloat162*)(hi + row * 1024 + tid * 4);
    __nv_bfloat162* pl = (__nv_bfloat162*)(lo + row * 1024 + tid * 4);
    ph[0] = __halves2bfloat162(h0, h1);
    ph[1] = __halves2bfloat162(h2, h3);
    pl[0] = __halves2bfloat162(__float2bfloat16(l0), __float2bfloat16(l1));
    pl[1] = __halves2bfloat162(__float2bfloat16(l2), __float2bfloat16(l3));
}

// ---------------------------------------------------------------------------
// Complex LayerNorm, in place on out = [2, B*S, D].
// ---------------------------------------------------------------------------
__global__ __launch_bounds__(256)
void complex_ln_kernel(float* __restrict__ out,
                       const float* __restrict__ a2,
                       const float* __restrict__ b2)
{
    const size_t row = blockIdx.x;
    float* pr = out + row * 1024;
    float* pi = out + MS + row * 1024;
    const int tid = threadIdx.x;

    float4 zr = ((float4*)pr)[tid];
    float4 zi = ((float4*)pi)[tid];

    float sv[5];
    sv[0] = zr.x + zr.y + zr.z + zr.w;
    sv[1] = zi.x + zi.y + zi.z + zi.w;
    sv[2] = zr.x*zr.x + zr.y*zr.y + zr.z*zr.z + zr.w*zr.w;
    sv[3] = zi.x*zi.x + zi.y*zi.y + zi.z*zi.z + zi.w*zi.w;
    sv[4] = zr.x*zi.x + zr.y*zi.y + zr.z*zi.z + zr.w*zi.w;

    #pragma unroll
    for (int u = 0; u < 5; u++)
        #pragma unroll
        for (int o = 16; o > 0; o >>= 1)
            sv[u] += __shfl_xor_sync(0xffffffffu, sv[u], o);

    __shared__ float red[5][8];
    __shared__ float fin[5];
    if ((tid & 31) == 0) {
        #pragma unroll
        for (int u = 0; u < 5; u++) red[u][tid >> 5] = sv[u];
    }
    __syncthreads();
    if (tid == 0) {
        #pragma unroll
        for (int u = 0; u < 5; u++) {
            float t = 0.f;
            #pragma unroll
            for (int wv = 0; wv < 8; wv++) t += red[u][wv];
            fin[u] = t;
        }
    }
    __syncthreads();

    const float invD = 1.0f / 1024.0f;
    const float mr = fin[0] * invD;
    const float mi = fin[1] * invD;
    const float err = fin[2] * invD - mr * mr;
    const float eii = fin[3] * invD - mi * mi;
    const float eri = fin[4] * invD - mr * mi;
    const float vr = err - eii + 1e-6f;
    const float vi = 2.0f * eri;
    const float rmod = sqrtf(vr * vr + vi * vi);
    const float sre = sqrtf(fmaxf(0.5f * (rmod + vr), 0.f));
    const float sim = copysignf(sqrtf(fmaxf(0.5f * (rmod - vr), 0.f)), vi);
    const float inv = 1.0f / fmaxf(rmod, 1e-30f);

    float4 ga = ((const float4*)a2)[tid];
    float4 gb = ((const float4*)b2)[tid];

    float4 yr, yi;
    {
        float ar = zr.x - mr, ai = zi.x - mi;
        yr.x = (ar * sre + ai * sim) * inv; yi.x = (ai * sre - ar * sim) * inv;
        ar = zr.y - mr; ai = zi.y - mi;
        yr.y = (ar * sre + ai * sim) * inv; yi.y = (ai * sre - ar * sim) * inv;
        ar = zr.z - mr; ai = zi.z - mi;
        yr.z = (ar * sre + ai * sim) * inv; yi.z = (ai * sre - ar * sim) * inv;
        ar = zr.w - mr; ai = zi.w - mi;
        yr.w = (ar * sre + ai * sim) * inv; yi.w = (ai * sre - ar * sim) * inv;
    }
    yr.x = ga.x * yr.x + gb.x; yi.x = ga.x * yi.x;
    yr.y = ga.y * yr.y + gb.y; yi.y = ga.y * yi.y;
    yr.z = ga.z * yr.z + gb.z; yi.z = ga.z * yi.z;
    yr.w = ga.w * yr.w + gb.w; yi.w = ga.w * yi.w;

    ((float4*)pr)[tid] = yr;
    ((float4*)pi)[tid] = yi;
}

// ---------------------------------------------------------------------------
extern "C" void kernel_launch(void* const* d_in, const int* in_sizes, int n_in,
                              void* d_out, int out_size)
{
    const float* X[6]  = { (const float*)d_in[0], (const float*)d_in[1],
                           (const float*)d_in[2], (const float*)d_in[3],
                           (const float*)d_in[4], (const float*)d_in[5] };
    const float* W[6]  = { (const float*)d_in[6],  (const float*)d_in[8],
                           (const float*)d_in[10], (const float*)d_in[12],
                           (const float*)d_in[14], (const float*)d_in[16] };
    const float* Bv[6] = { (const float*)d_in[7],  (const float*)d_in[9],
                           (const float*)d_in[11], (const float*)d_in[13],
                           (const float*)d_in[15], (const float*)d_in[17] };
    const float* a2 = (const float*)d_in[18];
    const float* b2 = (const float*)d_in[19];
    float* out = (float*)d_out;

    __nv_bfloat16 *xhi, *xlo, *whi, *wlo, *phi, *plo, *thi, *tlo, *ahi, *alo;
    float* scores;
    cudaGetSymbolAddress((void**)&xhi, g_xhi);
    cudaGetSymbolAddress((void**)&xlo, g_xlo);
    cudaGetSymbolAddress((void**)&whi, g_whi);
    cudaGetSymbolAddress((void**)&wlo, g_wlo);
    cudaGetSymbolAddress((void**)&phi, g_phi);
    cudaGetSymbolAddress((void**)&plo, g_plo);
    cudaGetSymbolAddress((void**)&thi, g_thi);
    cudaGetSymbolAddress((void**)&tlo, g_tlo);
    cudaGetSymbolAddress((void**)&ahi, g_ahi);
    cudaGetSymbolAddress((void**)&alo, g_alo);
    cudaGetSymbolAddress((void**)&scores, g_scores);

    cudaFuncSetAttribute(tc_gemm<0>,
        cudaFuncAttributeMaxDynamicSharedMemorySize, GSMEM);
    cudaFuncSetAttribute(tc_gemm<1>,
        cudaFuncAttributeMaxDynamicSharedMemorySize, GSMEM);

    // 1) split X and W into bf16 hi/lo planes
    for (int j = 0; j < 6; j++) {
        conv_split<<<(unsigned)(MS/4/256), 256>>>(
            (const float4*)X[j], (__nv_bfloat162*)(xhi + j*MS),
            (__nv_bfloat162*)(xlo + j*MS), MS/4);
        conv_split<<<(unsigned)(WS/4/256), 256>>>(
            (const float4*)W[j], (__nv_bfloat162*)(whi + j*WS),
            (__nv_bfloat162*)(wlo + j*WS), WS/4);
    }

    // 2) six projections (plain plane writes). kr/vr/vi -> temp slots.
    // final slots: 0 qr, 1 qi, 2 krT, 3 ki, 4 vrT, 5 viT
    {
        dim3 pg(8, 64, 1);     // N/128, M/256
        for (int j = 0; j < 6; j++) {
            SegPtrs sp{};
            sp.a[0] = xhi + j*MS; sp.a[1] = xlo + j*MS; sp.a[2] = xhi + j*MS;
            sp.b[0] = whi + j*WS; sp.b[1] = whi + j*WS; sp.b[2] = wlo + j*WS;
            __nv_bfloat16 *dh, *dl;
            if (j == 2)      { dh = thi + 0*MS; dl = tlo + 0*MS; }
            else if (j == 4) { dh = thi + 1*MS; dl = tlo + 1*MS; }
            else if (j == 5) { dh = thi + 2*MS; dl = tlo + 2*MS; }
            else             { dh = phi + j*MS; dl = plo + j*MS; }
            tc_gemm<1><<<pg, 256, GSMEM>>>(sp, 3, 0, 0, nullptr, 0, 1.f,
                                           Bv[j], dh, dl);
        }
    }

    // 2b) coalesced bf16 transposes: temp -> slots 2 (krT), 4 (vrT), 5 (viT)
    {
        dim3 tg(16, 16, BATCH);
        dim3 tb(32, 8);
        transpose_bf16<<<tg, tb>>>(thi + 0*MS, phi + 2*MS);
        transpose_bf16<<<tg, tb>>>(tlo + 0*MS, plo + 2*MS);
        transpose_bf16<<<tg, tb>>>(thi + 1*MS, phi + 4*MS);
        transpose_bf16<<<tg, tb>>>(tlo + 1*MS, plo + 4*MS);
        transpose_bf16<<<tg, tb>>>(thi + 2*MS, phi + 5*MS);
        transpose_bf16<<<tg, tb>>>(tlo + 2*MS, plo + 5*MS);
    }

    // 3) scores = (qr@krT^T + qi@ki^T) / 8  -> 6 segments, one GEMM
    {
        SegPtrs sp{};
        sp.a[0] = phi + 0*MS; sp.a[1] = plo + 0*MS; sp.a[2] = phi + 0*MS;
        sp.b[0] = phi + 2*MS; sp.b[1] = phi + 2*MS; sp.b[2] = plo + 2*MS;
        sp.a[3] = phi + 1*MS; sp.a[4] = plo + 1*MS; sp.a[5] = phi + 1*MS;
        sp.b[3] = phi + 3*MS; sp.b[4] = phi + 3*MS; sp.b[5] = plo + 3*MS;
        dim3 sg(8, 4, BATCH);  // N/128, S/256, B
        tc_gemm<0><<<sg, 256, GSMEM>>>(sp, 6, SD, SD, scores, SD, 0.125f,
                                       nullptr, nullptr, nullptr);
    }

    // 4) softmax -> attn hi/lo planes
    softmax_split<<<MTOT, 256>>>(scores, ahi, alo);

    // 5) out_r = attn @ vrT^T, out_i = attn @ viT^T (fp32 into d_out)
    {
        dim3 og(8, 4, BATCH);
        SegPtrs sr{};
        sr.a[0] = ahi; sr.a[1] = alo; sr.a[2] = ahi;
        sr.b[0] = phi + 4*MS; sr.b[1] = phi + 4*MS; sr.b[2] = plo + 4*MS;
        tc_gemm<0><<<og, 256, GSMEM>>>(sr, 3, SD, SD, out, SD, 1.f,
                                       nullptr, nullptr, nullptr);
        SegPtrs si{};
        si.a[0] = ahi; si.a[1] = alo; si.a[2] = ahi;
        si.b[0] = phi + 5*MS; si.b[1] = phi + 5*MS; si.b[2] = plo + 5*MS;
        tc_gemm<0><<<og, 256, GSMEM>>>(si, 3, SD, SD, out + MS, SD, 1.f,
                                       nullptr, nullptr, nullptr);
    }

    // 6) complex LayerNorm in place on d_out
    complex_ln_kernel<<<MTOT, 256>>>(out, a2, b2);
}

// round 11
// speedup vs baseline: 1.2330x; 1.2330x over previous
#include <cuda_runtime.h>
#include <cuda_fp16.h>
#include <math.h>
#include <stdint.h>

// Problem constants
#define BATCH 16
#define SEQ   1024
#define DIM   1024
#define MTOT  (BATCH*SEQ)            // 16384
#define MS    ((size_t)MTOT*DIM)     // 16777216
#define SD    ((size_t)SEQ*DIM)      // per-batch stride
#define WS    ((size_t)DIM*DIM)

// fp16 hi/lo planes (device globals; cudaMalloc forbidden)
__device__ __half g_xhi[6*MS], g_xlo[6*MS];
__device__ __half g_whi[6*WS], g_wlo[6*WS];
// proj planes, slots: 0 qr, 1 qi, 2 krT, 3 ki, 4 vrT, 5 viT
__device__ __half g_phi[6*MS], g_plo[6*MS];
// temp (untransposed) planes for kr, vr, vi
__device__ __half g_thi[3*MS], g_tlo[3*MS];
__device__ __half g_ahi[MS],  g_alo[MS];
__device__ float g_scores[(size_t)BATCH*SEQ*SEQ];

// ---------------------------------------------------------------------------
// helpers
// ---------------------------------------------------------------------------
__device__ __forceinline__ uint32_t smem_u32(const void* p) {
    uint32_t r;
    asm("{ .reg .u64 t; cvta.to.shared.u64 t, %1; cvt.u32.u64 %0, t; }"
        : "=r"(r) : "l"(p));
    return r;
}

__device__ __forceinline__ void cp16(uint32_t d, const void* s) {
    asm volatile("cp.async.cg.shared.global [%0], [%1], 16;" :: "r"(d), "l"(s));
}

__device__ __forceinline__ void ldmx4(uint32_t& r0, uint32_t& r1,
                                      uint32_t& r2, uint32_t& r3, uint32_t a) {
    asm volatile("ldmatrix.sync.aligned.m8n8.x4.shared.b16 {%0,%1,%2,%3}, [%4];"
                 : "=r"(r0), "=r"(r1), "=r"(r2), "=r"(r3) : "r"(a));
}

// fp16 x fp16 -> f32 accumulate (rt ~16)
__device__ __forceinline__ void mma16816(float* c, const uint32_t* a,
                                         const uint32_t* b) {
    asm volatile(
        "mma.sync.aligned.m16n8k16.row.col.f32.f16.f16.f32 "
        "{%0,%1,%2,%3}, {%4,%5,%6,%7}, {%8,%9}, {%0,%1,%2,%3};"
        : "+f"(c[0]), "+f"(c[1]), "+f"(c[2]), "+f"(c[3])
        : "r"(a[0]), "r"(a[1]), "r"(a[2]), "r"(a[3]), "r"(b[0]), "r"(b[1]));
}

// fp16 x fp16 -> f16 accumulate (rt ~8, 2x rate) — used for cross terms only
__device__ __forceinline__ void mma16816h(uint32_t* c, const uint32_t* a,
                                          const uint32_t* b) {
    asm volatile(
        "mma.sync.aligned.m16n8k16.row.col.f16.f16.f16.f16 "
        "{%0,%1}, {%2,%3,%4,%5}, {%6,%7}, {%0,%1};"
        : "+r"(c[0]), "+r"(c[1])
        : "r"(a[0]), "r"(a[1]), "r"(a[2]), "r"(a[3]), "r"(b[0]), "r"(b[1]));
}

__device__ __forceinline__ void fsplit(float x, __half& h, float& l) {
    h = __float2half_rn(x);
    l = x - __half2float(h);
}

// ---------------------------------------------------------------------------
// fp32 -> (hi, lo) fp16 planes, elementwise
// ---------------------------------------------------------------------------
__global__ __launch_bounds__(256)
void conv_split(const float4* __restrict__ in, __half2* __restrict__ hi,
                __half2* __restrict__ lo, size_t n4)
{
    size_t i = (size_t)blockIdx.x * 256 + threadIdx.x;
    if (i >= n4) return;
    float4 v = in[i];
    __half h0, h1, h2, h3; float l0, l1, l2, l3;
    fsplit(v.x, h0, l0); fsplit(v.y, h1, l1);
    fsplit(v.z, h2, l2); fsplit(v.w, h3, l3);
    hi[2*i]   = __halves2half2(h0, h1);
    hi[2*i+1] = __halves2half2(h2, h3);
    lo[2*i]   = __halves2half2(__float2half_rn(l0), __float2half_rn(l1));
    lo[2*i+1] = __halves2half2(__float2half_rn(l2), __float2half_rn(l3));
}

// ---------------------------------------------------------------------------
// Coalesced per-batch 1024x1024 fp16 transpose (64x64 smem tile, padded).
// ---------------------------------------------------------------------------
__global__ __launch_bounds__(256)
void transpose_h16(const __half* __restrict__ src, __half* __restrict__ dst)
{
    __shared__ __half t[64][66];
    const size_t bz = blockIdx.z;
    const __half* s = src + bz * SD;
    __half* d = dst + bz * SD;

    const int x = blockIdx.x * 64 + threadIdx.x * 2;
    const int y = blockIdx.y * 64 + threadIdx.y;
    #pragma unroll
    for (int j = 0; j < 64; j += 8) {
        __half2 v = *(const __half2*)(s + (size_t)(y + j) * 1024 + x);
        t[threadIdx.y + j][threadIdx.x * 2]     = __low2half(v);
        t[threadIdx.y + j][threadIdx.x * 2 + 1] = __high2half(v);
    }
    __syncthreads();
    const int xo = blockIdx.y * 64 + threadIdx.x * 2;
    const int yo = blockIdx.x * 64 + threadIdx.y;
    #pragma unroll
    for (int j = 0; j < 64; j += 8) {
        __half2 v = __halves2half2(
            t[threadIdx.x * 2][threadIdx.y + j],
            t[threadIdx.x * 2 + 1][threadIdx.y + j]);
        *(__half2*)(d + (size_t)(yo + j) * 1024 + xo) = v;
    }
}

// ---------------------------------------------------------------------------
// Split-fp16 HMMA GEMM (3-stage cp.async ring, mixed-precision accumulate).
// C[m,n] = sum_seg Aseg[m,:] . Bseg[n,:]  (row-major, ld=1024, K=1024/seg)
// Segments [0, ncross) accumulate in f16 (2x mma rate; small cross terms),
// segments [ncross, ncross+nmain) accumulate in f32. hacc merged into acc
// between the phases (phase-split also keeps register liveness low).
// Tile 128x128, 8 warps (4x2), warp tile 32x64, mma m16n8k16.
// Epilogues: 0 = fp32*alpha, 1 = +bias -> split hi/lo fp16 planes.
// ---------------------------------------------------------------------------
#define RS 40                     // smem row stride in halves (80B)
#define OPBYTES (128*RS*2)        // 10240 per operand per stage
#define NSTAGE 3
#define GSMEM (NSTAGE*2*OPBYTES)  // 61440

struct SegPtrs { const __half* a[6]; const __half* b[6]; };

template<int EPI>
__global__ __launch_bounds__(256, 2)
void tc_gemm(SegPtrs segs, int ncross, int nmain, size_t sA, size_t sB,
             float* __restrict__ Cf, size_t sC, float alpha,
             const float* __restrict__ bias,
             __half* __restrict__ hiP, __half* __restrict__ loP)
{
    extern __shared__ __align__(128) char sm[];
    __shared__ const __half* sAp[6];
    __shared__ const __half* sBp[6];

    const int tid = threadIdx.x;
    const int m0 = blockIdx.y * 128;
    const int n0 = blockIdx.x * 128;
    const size_t bz = blockIdx.z;
    const int nseg = ncross + nmain;

    if (tid < 6 && tid < nseg) {
        sAp[tid] = segs.a[tid] + bz * sA + (size_t)m0 * 1024;
        sBp[tid] = segs.b[tid] + bz * sB + (size_t)n0 * 1024;
    }
    __syncthreads();

    const uint32_t smb = smem_u32(sm);
    const int r0 = tid >> 2, c0 = tid & 3;
    const int NITc = ncross * 32;
    const int NIT = nseg * 32;

    auto issue = [&](int it) {
        const int seg = it >> 5, kc = it & 31;
        const uint32_t st = smb + (uint32_t)(it % NSTAGE) * (2 * OPBYTES);
        const __half* ga = sAp[seg] + kc * 32;
        const __half* gb = sBp[seg] + kc * 32;
        cp16(st + r0 * 80 + c0 * 16,            ga + (size_t)r0 * 1024 + c0 * 8);
        cp16(st + (r0 + 64) * 80 + c0 * 16,     ga + (size_t)(r0 + 64) * 1024 + c0 * 8);
        cp16(st + OPBYTES + r0 * 80 + c0 * 16,        gb + (size_t)r0 * 1024 + c0 * 8);
        cp16(st + OPBYTES + (r0 + 64) * 80 + c0 * 16, gb + (size_t)(r0 + 64) * 1024 + c0 * 8);
    };

    const int lane = tid & 31, w = tid >> 5;
    const int wm = (w >> 1) * 32;
    const int wn = (w & 1) * 64;
    const uint32_t lmo = (uint32_t)((lane & 15) * 80 + (lane >> 4) * 16);

    issue(0);
    asm volatile("cp.async.commit_group;" ::: "memory");
    issue(1);
    asm volatile("cp.async.commit_group;" ::: "memory");

    // ---- Phase 1: cross terms, f16 accumulators (2x mma rate) ----
    uint32_t hacc[2][8][2];
    #pragma unroll
    for (int i = 0; i < 2; i++)
        #pragma unroll
        for (int j = 0; j < 8; j++) { hacc[i][j][0] = 0u; hacc[i][j][1] = 0u; }

    for (int it = 0; it < NITc; ++it) {
        asm volatile("cp.async.wait_group 1;" ::: "memory");
        __syncthreads();
        if (it + 2 < NIT) issue(it + 2);
        asm volatile("cp.async.commit_group;" ::: "memory");

        const uint32_t stg = smb + (uint32_t)(it % NSTAGE) * (2 * OPBYTES);
        const uint32_t sa = stg + wm * 80 + lmo;
        const uint32_t sb = stg + OPBYTES + wn * 80 + lmo;

        #pragma unroll
        for (int ks = 0; ks < 2; ks++) {
            uint32_t A0[4], A1[4], Bf[8][2];
            ldmx4(A0[0], A0[1], A0[2], A0[3], sa + ks * 32);
            ldmx4(A1[0], A1[1], A1[2], A1[3], sa + 1280 + ks * 32);
            #pragma unroll
            for (int q = 0; q < 4; q++) {
                uint32_t t0, t1, t2, t3;
                ldmx4(t0, t1, t2, t3, sb + q * 1280 + ks * 32);
                Bf[2*q][0] = t0; Bf[2*q][1] = t2;
                Bf[2*q+1][0] = t1; Bf[2*q+1][1] = t3;
            }
            #pragma unroll
            for (int nt = 0; nt < 8; nt++) {
                mma16816h(hacc[0][nt], A0, Bf[nt]);
                mma16816h(hacc[1][nt], A1, Bf[nt]);
            }
        }
    }

    // ---- Merge f16 cross accumulators into f32 accumulators ----
    float acc[2][8][4];
    #pragma unroll
    for (int i = 0; i < 2; i++)
        #pragma unroll
        for (int j = 0; j < 8; j++) {
            float2 p0 = __half22float2(*(__half2*)&hacc[i][j][0]);
            float2 p1 = __half22float2(*(__half2*)&hacc[i][j][1]);
            acc[i][j][0] = p0.x; acc[i][j][1] = p0.y;
            acc[i][j][2] = p1.x; acc[i][j][3] = p1.y;
        }

    // ---- Phase 2: hi*hi main terms, f32 accumulators ----
    for (int it = NITc; it < NIT; ++it) {
        asm volatile("cp.async.wait_group 1;" ::: "memory");
        __syncthreads();
        if (it + 2 < NIT) issue(it + 2);
        asm volatile("cp.async.commit_group;" ::: "memory");

        const uint32_t stg = smb + (uint32_t)(it % NSTAGE) * (2 * OPBYTES);
        const uint32_t sa = stg + wm * 80 + lmo;
        const uint32_t sb = stg + OPBYTES + wn * 80 + lmo;

        #pragma unroll
        for (int ks = 0; ks < 2; ks++) {
            uint32_t A0[4], A1[4], Bf[8][2];
            ldmx4(A0[0], A0[1], A0[2], A0[3], sa + ks * 32);
            ldmx4(A1[0], A1[1], A1[2], A1[3], sa + 1280 + ks * 32);
            #pragma unroll
            for (int q = 0; q < 4; q++) {
                uint32_t t0, t1, t2, t3;
                ldmx4(t0, t1, t2, t3, sb + q * 1280 + ks * 32);
                Bf[2*q][0] = t0; Bf[2*q][1] = t2;
                Bf[2*q+1][0] = t1; Bf[2*q+1][1] = t3;
            }
            #pragma unroll
            for (int nt = 0; nt < 8; nt++) {
                mma16816(acc[0][nt], A0, Bf[nt]);
                mma16816(acc[1][nt], A1, Bf[nt]);
            }
        }
    }

    // Epilogue. Frag: g=lane>>2, t4=lane&3: c0,c1 -> (row g, cols 2t4,2t4+1),
    // c2,c3 -> (row g+8, same cols).
    const int g = lane >> 2, t4 = lane & 3;
    #pragma unroll
    for (int mt = 0; mt < 2; mt++) {
        #pragma unroll
        for (int nt = 0; nt < 8; nt++) {
            const int rowA = m0 + wm + mt * 16 + g;
            const int rowB = rowA + 8;
            const int col  = n0 + wn + nt * 8 + 2 * t4;
            float c0 = acc[mt][nt][0], c1 = acc[mt][nt][1];
            float c2 = acc[mt][nt][2], c3 = acc[mt][nt][3];
            if (EPI == 0) {
                float2 v0 = make_float2(c0 * alpha, c1 * alpha);
                float2 v1 = make_float2(c2 * alpha, c3 * alpha);
                *(float2*)(Cf + bz * sC + (size_t)rowA * 1024 + col) = v0;
                *(float2*)(Cf + bz * sC + (size_t)rowB * 1024 + col) = v1;
            } else {
                const float b0v = bias[col], b1v = bias[col + 1];
                const float v0 = c0 + b0v, v1 = c1 + b1v;
                const float v2 = c2 + b0v, v3 = c3 + b1v;
                __half h0, h1, h2, h3; float l0, l1, l2, l3;
                fsplit(v0, h0, l0); fsplit(v1, h1, l1);
                fsplit(v2, h2, l2); fsplit(v3, h3, l3);
                *(__half2*)(hiP + (size_t)rowA * 1024 + col) = __halves2half2(h0, h1);
                *(__half2*)(hiP + (size_t)rowB * 1024 + col) = __halves2half2(h2, h3);
                *(__half2*)(loP + (size_t)rowA * 1024 + col) =
                    __halves2half2(__float2half_rn(l0), __float2half_rn(l1));
                *(__half2*)(loP + (size_t)rowB * 1024 + col) =
                    __halves2half2(__float2half_rn(l2), __float2half_rn(l3));
            }
        }
    }
}

// ---------------------------------------------------------------------------
// Row softmax over 1024, writes attn hi/lo fp16 planes.
// ---------------------------------------------------------------------------
__global__ __launch_bounds__(256)
void softmax_split(const float* __restrict__ s, __half* __restrict__ hi,
                   __half* __restrict__ lo)
{
    const size_t row = blockIdx.x;
    const float4* p = (const float4*)(s + row * 1024);
    const int tid = threadIdx.x;

    float4 v = p[tid];
    float m = fmaxf(fmaxf(v.x, v.y), fmaxf(v.z, v.w));
    #pragma unroll
    for (int o = 16; o > 0; o >>= 1)
        m = fmaxf(m, __shfl_xor_sync(0xffffffffu, m, o));

    __shared__ float red[8];
    __shared__ float fin[2];
    if ((tid & 31) == 0) red[tid >> 5] = m;
    __syncthreads();
    if (tid < 32) {
        float t = (tid < 8) ? red[tid] : -3.4e38f;
        #pragma unroll
        for (int o = 4; o > 0; o >>= 1)
            t = fmaxf(t, __shfl_xor_sync(0xffffffffu, t, o));
        if (tid == 0) fin[0] = t;
    }
    __syncthreads();
    m = fin[0];

    v.x = expf(v.x - m); v.y = expf(v.y - m);
    v.z = expf(v.z - m); v.w = expf(v.w - m);
    float sum = v.x + v.y + v.z + v.w;
    #pragma unroll
    for (int o = 16; o > 0; o >>= 1)
        sum += __shfl_xor_sync(0xffffffffu, sum, o);
    if ((tid & 31) == 0) red[tid >> 5] = sum;
    __syncthreads();
    if (tid < 32) {
        float t = (tid < 8) ? red[tid] : 0.f;
        #pragma unroll
        for (int o = 4; o > 0; o >>= 1)
            t += __shfl_xor_sync(0xffffffffu, t, o);
        if (tid == 0) fin[1] = t;
    }
    __syncthreads();
    const float inv = 1.0f / fin[1];
    v.x *= inv; v.y *= inv; v.z *= inv; v.w *= inv;

    __half h0, h1, h2, h3; float l0, l1, l2, l3;
    fsplit(v.x, h0, l0); fsplit(v.y, h1, l1);
    fsplit(v.z, h2, l2); fsplit(v.w, h3, l3);
    __half2* ph = (__half2*)(hi + row * 1024 + tid * 4);
    __half2* pl = (__half2*)(lo + row * 1024 + tid * 4);
    ph[0] = __halves2half2(h0, h1);
    ph[1] = __halves2half2(h2, h3);
    pl[0] = __halves2half2(__float2half_rn(l0), __float2half_rn(l1));
    pl[1] = __halves2half2(__float2half_rn(l2), __float2half_rn(l3));
}

// ---------------------------------------------------------------------------
// Complex LayerNorm, in place on out = [2, B*S, D].
// ---------------------------------------------------------------------------
__global__ __launch_bounds__(256)
void complex_ln_kernel(float* __restrict__ out,
                       const float* __restrict__ a2,
                       const float* __restrict__ b2)
{
    const size_t row = blockIdx.x;
    float* pr = out + row * 1024;
    float* pi = out + MS + row * 1024;
    const int tid = threadIdx.x;

    float4 zr = ((float4*)pr)[tid];
    float4 zi = ((float4*)pi)[tid];

    float sv[5];
    sv[0] = zr.x + zr.y + zr.z + zr.w;
    sv[1] = zi.x + zi.y + zi.z + zi.w;
    sv[2] = zr.x*zr.x + zr.y*zr.y + zr.z*zr.z + zr.w*zr.w;
    sv[3] = zi.x*zi.x + zi.y*zi.y + zi.z*zi.z + zi.w*zi.w;
    sv[4] = zr.x*zi.x + zr.y*zi.y + zr.z*zi.z + zr.w*zi.w;

    #pragma unroll
    for (int u = 0; u < 5; u++)
        #pragma unroll
        for (int o = 16; o > 0; o >>= 1)
            sv[u] += __shfl_xor_sync(0xffffffffu, sv[u], o);

    __shared__ float red[5][8];
    __shared__ float fin[5];
    if ((tid & 31) == 0) {
        #pragma unroll
        for (int u = 0; u < 5; u++) red[u][tid >> 5] = sv[u];
    }
    __syncthreads();
    if (tid == 0) {
        #pragma unroll
        for (int u = 0; u < 5; u++) {
            float t = 0.f;
            #pragma unroll
            for (int wv = 0; wv < 8; wv++) t += red[u][wv];
            fin[u] = t;
        }
    }
    __syncthreads();

    const float invD = 1.0f / 1024.0f;
    const float mr = fin[0] * invD;
    const float mi = fin[1] * invD;
    const float err = fin[2] * invD - mr * mr;
    const float eii = fin[3] * invD - mi * mi;
    const float eri = fin[4] * invD - mr * mi;
    const float vr = err - eii + 1e-6f;
    const float vi = 2.0f * eri;
    const float rmod = sqrtf(vr * vr + vi * vi);
    const float sre = sqrtf(fmaxf(0.5f * (rmod + vr), 0.f));
    const float sim = copysignf(sqrtf(fmaxf(0.5f * (rmod - vr), 0.f)), vi);
    const float inv = 1.0f / fmaxf(rmod, 1e-30f);

    float4 ga = ((const float4*)a2)[tid];
    float4 gb = ((const float4*)b2)[tid];

    float4 yr, yi;
    {
        float ar = zr.x - mr, ai = zi.x - mi;
        yr.x = (ar * sre + ai * sim) * inv; yi.x = (ai * sre - ar * sim) * inv;
        ar = zr.y - mr; ai = zi.y - mi;
        yr.y = (ar * sre + ai * sim) * inv; yi.y = (ai * sre - ar * sim) * inv;
        ar = zr.z - mr; ai = zi.z - mi;
        yr.z = (ar * sre + ai * sim) * inv; yi.z = (ai * sre - ar * sim) * inv;
        ar = zr.w - mr; ai = zi.w - mi;
        yr.w = (ar * sre + ai * sim) * inv; yi.w = (ai * sre - ar * sim) * inv;
    }
    yr.x = ga.x * yr.x + gb.x; yi.x = ga.x * yi.x;
    yr.y = ga.y * yr.y + gb.y; yi.y = ga.y * yi.y;
    yr.z = ga.z * yr.z + gb.z; yi.z = ga.z * yi.z;
    yr.w = ga.w * yr.w + gb.w; yi.w = ga.w * yi.w;

    ((float4*)pr)[tid] = yr;
    ((float4*)pi)[tid] = yi;
}

// ---------------------------------------------------------------------------
extern "C" void kernel_launch(void* const* d_in, const int* in_sizes, int n_in,
                              void* d_out, int out_size)
{
    const float* X[6]  = { (const float*)d_in[0], (const float*)d_in[1],
                           (const float*)d_in[2], (const float*)d_in[3],
                           (const float*)d_in[4], (const float*)d_in[5] };
    const float* W[6]  = { (const float*)d_in[6],  (const float*)d_in[8],
                           (const float*)d_in[10], (const float*)d_in[12],
                           (const float*)d_in[14], (const float*)d_in[16] };
    const float* Bv[6] = { (const float*)d_in[7],  (const float*)d_in[9],
                           (const float*)d_in[11], (const float*)d_in[13],
                           (const float*)d_in[15], (const float*)d_in[17] };
    const float* a2 = (const float*)d_in[18];
    const float* b2 = (const float*)d_in[19];
    float* out = (float*)d_out;

    __half *xhi, *xlo, *whi, *wlo, *phi, *plo, *thi, *tlo, *ahi, *alo;
    float* scores;
    cudaGetSymbolAddress((void**)&xhi, g_xhi);
    cudaGetSymbolAddress((void**)&xlo, g_xlo);
    cudaGetSymbolAddress((void**)&whi, g_whi);
    cudaGetSymbolAddress((void**)&wlo, g_wlo);
    cudaGetSymbolAddress((void**)&phi, g_phi);
    cudaGetSymbolAddress((void**)&plo, g_plo);
    cudaGetSymbolAddress((void**)&thi, g_thi);
    cudaGetSymbolAddress((void**)&tlo, g_tlo);
    cudaGetSymbolAddress((void**)&ahi, g_ahi);
    cudaGetSymbolAddress((void**)&alo, g_alo);
    cudaGetSymbolAddress((void**)&scores, g_scores);

    cudaFuncSetAttribute(tc_gemm<0>,
        cudaFuncAttributeMaxDynamicSharedMemorySize, GSMEM);
    cudaFuncSetAttribute(tc_gemm<1>,
        cudaFuncAttributeMaxDynamicSharedMemorySize, GSMEM);

    // 1) split X and W into fp16 hi/lo planes
    for (int j = 0; j < 6; j++) {
        conv_split<<<(unsigned)(MS/4/256), 256>>>(
            (const float4*)X[j], (__half2*)(xhi + j*MS),
            (__half2*)(xlo + j*MS), MS/4);
        conv_split<<<(unsigned)(WS/4/256), 256>>>(
            (const float4*)W[j], (__half2*)(whi + j*WS),
            (__half2*)(wlo + j*WS), WS/4);
    }

    // 2) six projections. Cross segs (f16 acc) first, then hi*hi (f32 acc).
    // kr/vr/vi -> temp slots; final slots: 0 qr, 1 qi, 2 krT, 3 ki, 4 vrT, 5 viT
    {
        dim3 pg(8, 128, 1);
        for (int j = 0; j < 6; j++) {
            SegPtrs sp{};
            sp.a[0] = xlo + j*MS; sp.b[0] = whi + j*WS;   // cross
            sp.a[1] = xhi + j*MS; sp.b[1] = wlo + j*WS;   // cross
            sp.a[2] = xhi + j*MS; sp.b[2] = whi + j*WS;   // main
            __half *dh, *dl;
            if (j == 2)      { dh = thi + 0*MS; dl = tlo + 0*MS; }
            else if (j == 4) { dh = thi + 1*MS; dl = tlo + 1*MS; }
            else if (j == 5) { dh = thi + 2*MS; dl = tlo + 2*MS; }
            else             { dh = phi + j*MS; dl = plo + j*MS; }
            tc_gemm<1><<<pg, 256, GSMEM>>>(sp, 2, 1, 0, 0, nullptr, 0, 1.f,
                                           Bv[j], dh, dl);
        }
    }

    // 2b) coalesced fp16 transposes: temp -> slots 2 (krT), 4 (vrT), 5 (viT)
    {
        dim3 tg(16, 16, BATCH);
        dim3 tb(32, 8);
        transpose_h16<<<tg, tb>>>(thi + 0*MS, phi + 2*MS);
        transpose_h16<<<tg, tb>>>(tlo + 0*MS, plo + 2*MS);
        transpose_h16<<<tg, tb>>>(thi + 1*MS, phi + 4*MS);
        transpose_h16<<<tg, tb>>>(tlo + 1*MS, plo + 4*MS);
        transpose_h16<<<tg, tb>>>(thi + 2*MS, phi + 5*MS);
        transpose_h16<<<tg, tb>>>(tlo + 2*MS, plo + 5*MS);
    }

    // 3) scores = (qr@krT^T + qi@ki^T) / 8: 4 cross (f16 acc) + 2 main (f32)
    {
        SegPtrs sp{};
        sp.a[0] = plo + 0*MS; sp.b[0] = phi + 2*MS;   // cross qr_lo . krT_hi
        sp.a[1] = phi + 0*MS; sp.b[1] = plo + 2*MS;   // cross qr_hi . krT_lo
        sp.a[2] = plo + 1*MS; sp.b[2] = phi + 3*MS;   // cross qi_lo . ki_hi
        sp.a[3] = phi + 1*MS; sp.b[3] = plo + 3*MS;   // cross qi_hi . ki_lo
        sp.a[4] = phi + 0*MS; sp.b[4] = phi + 2*MS;   // main  qr_hi . krT_hi
        sp.a[5] = phi + 1*MS; sp.b[5] = phi + 3*MS;   // main  qi_hi . ki_hi
        dim3 sg(8, 8, BATCH);
        tc_gemm<0><<<sg, 256, GSMEM>>>(sp, 4, 2, SD, SD, scores, SD, 0.125f,
                                       nullptr, nullptr, nullptr);
    }

    // 4) softmax -> attn hi/lo planes
    softmax_split<<<MTOT, 256>>>(scores, ahi, alo);

    // 5) out_r = attn @ vrT^T, out_i = attn @ viT^T (fp32 into d_out)
    {
        dim3 og(8, 8, BATCH);
        SegPtrs sr{};
        sr.a[0] = alo; sr.b[0] = phi + 4*MS;          // cross
        sr.a[1] = ahi; sr.b[1] = plo + 4*MS;          // cross
        sr.a[2] = ahi; sr.b[2] = phi + 4*MS;          // main
        tc_gemm<0><<<og, 256, GSMEM>>>(sr, 2, 1, SD, SD, out, SD, 1.f,
                                       nullptr, nullptr, nullptr);
        SegPtrs si{};
        si.a[0] = alo; si.b[0] = phi + 5*MS;          // cross
        si.a[1] = ahi; si.b[1] = plo + 5*MS;          // cross
        si.a[2] = ahi; si.b[2] = phi + 5*MS;          // main
        tc_gemm<0><<<og, 256, GSMEM>>>(si, 2, 1, SD, SD, out + MS, SD, 1.f,
                                       nullptr, nullptr, nullptr);
    }

    // 6) complex LayerNorm in place on d_out
    complex_ln_kernel<<<MTOT, 256>>>(out, a2, b2);
}

// round 15
// speedup vs baseline: 1.3381x; 1.0852x over previous
#include <cuda_runtime.h>
#include <cuda_fp16.h>
#include <math.h>
#include <stdint.h>

// Problem constants
#define BATCH 16
#define SEQ   1024
#define DIM   1024
#define MTOT  (BATCH*SEQ)            // 16384
#define MS    ((size_t)MTOT*DIM)     // 16777216
#define SD    ((size_t)SEQ*DIM)      // per-batch stride
#define WS    ((size_t)DIM*DIM)

// fp16 hi/lo planes (device globals; cudaMalloc forbidden)
__device__ __half g_xhi[6*MS], g_xlo[6*MS];
__device__ __half g_whi[6*WS], g_wlo[6*WS];
// proj planes, slots: 0 qr, 1 qi, 2 krT, 3 ki, 4 vrT, 5 viT
__device__ __half g_phi[6*MS], g_plo[6*MS];
// temp (untransposed) planes for kr, vr, vi
__device__ __half g_thi[3*MS], g_tlo[3*MS];
__device__ __half g_ahi[MS],  g_alo[MS];
__device__ float g_scores[(size_t)BATCH*SEQ*SEQ];

struct Ptr6  { const float* p[6]; };

// ---------------------------------------------------------------------------
// helpers
// ---------------------------------------------------------------------------
__device__ __forceinline__ uint32_t smem_u32(const void* p) {
    uint32_t r;
    asm("{ .reg .u64 t; cvta.to.shared.u64 t, %1; cvt.u32.u64 %0, t; }"
        : "=r"(r) : "l"(p));
    return r;
}

__device__ __forceinline__ void cp16(uint32_t d, const void* s) {
    asm volatile("cp.async.cg.shared.global [%0], [%1], 16;" :: "r"(d), "l"(s));
}

__device__ __forceinline__ void ldmx4(uint32_t& r0, uint32_t& r1,
                                      uint32_t& r2, uint32_t& r3, uint32_t a) {
    asm volatile("ldmatrix.sync.aligned.m8n8.x4.shared.b16 {%0,%1,%2,%3}, [%4];"
                 : "=r"(r0), "=r"(r1), "=r"(r2), "=r"(r3) : "r"(a));
}

// fp16 x fp16 -> f32 accumulate
__device__ __forceinline__ void mma16816(float* c, const uint32_t* a,
                                         const uint32_t* b) {
    asm volatile(
        "mma.sync.aligned.m16n8k16.row.col.f32.f16.f16.f32 "
        "{%0,%1,%2,%3}, {%4,%5,%6,%7}, {%8,%9}, {%0,%1,%2,%3};"
        : "+f"(c[0]), "+f"(c[1]), "+f"(c[2]), "+f"(c[3])
        : "r"(a[0]), "r"(a[1]), "r"(a[2]), "r"(a[3]), "r"(b[0]), "r"(b[1]));
}

// fp16 x fp16 -> f16 accumulate — small cross terms only
__device__ __forceinline__ void mma16816h(uint32_t* c, const uint32_t* a,
                                          const uint32_t* b) {
    asm volatile(
        "mma.sync.aligned.m16n8k16.row.col.f16.f16.f16.f16 "
        "{%0,%1}, {%2,%3,%4,%5}, {%6,%7}, {%0,%1};"
        : "+r"(c[0]), "+r"(c[1])
        : "r"(a[0]), "r"(a[1]), "r"(a[2]), "r"(a[3]), "r"(b[0]), "r"(b[1]));
}

__device__ __forceinline__ void fsplit(float x, __half& h, float& l) {
    h = __float2half_rn(x);
    l = x - __half2float(h);
}

// ---------------------------------------------------------------------------
// fp32 -> (hi, lo) fp16 planes, 6 tensors in one launch (z = tensor index)
// ---------------------------------------------------------------------------
__global__ __launch_bounds__(256)
void conv_split6(Ptr6 in, __half2* __restrict__ hiBase,
                 __half2* __restrict__ loBase, size_t plane4, size_t n4)
{
    const int j = blockIdx.z;
    size_t i = (size_t)blockIdx.x * 256 + threadIdx.x;
    if (i >= n4) return;
    const float4* src = (const float4*)in.p[j];
    __half2* hi = hiBase + j * plane4 * 2;
    __half2* lo = loBase + j * plane4 * 2;
    float4 v = src[i];
    __half h0, h1, h2, h3; float l0, l1, l2, l3;
    fsplit(v.x, h0, l0); fsplit(v.y, h1, l1);
    fsplit(v.z, h2, l2); fsplit(v.w, h3, l3);
    hi[2*i]   = __halves2half2(h0, h1);
    hi[2*i+1] = __halves2half2(h2, h3);
    lo[2*i]   = __halves2half2(__float2half_rn(l0), __float2half_rn(l1));
    lo[2*i+1] = __halves2half2(__float2half_rn(l2), __float2half_rn(l3));
}

// ---------------------------------------------------------------------------
// Coalesced per-batch 1024x1024 fp16 transpose; 6 plane-jobs x 16 batches
// merged into one launch (z = job*16 + batch).
// jobs: 0 thi0->phi[2], 1 tlo0->plo[2], 2 thi1->phi[4], 3 tlo1->plo[4],
//       4 thi2->phi[5], 5 tlo2->plo[5]
// ---------------------------------------------------------------------------
__global__ __launch_bounds__(256)
void transpose6(const __half* __restrict__ thiB, const __half* __restrict__ tloB,
                __half* __restrict__ phiB, __half* __restrict__ ploB)
{
    __shared__ __half t[64][66];
    const int z = blockIdx.z;
    const int job = z >> 4;
    const size_t bz = z & 15;
    const int tslot = job >> 1;                   // 0,1,2
    const int slot = (tslot == 0) ? 2 : (tslot == 1) ? 4 : 5;
    const __half* s = ((job & 1) ? tloB : thiB) + (size_t)tslot * MS + bz * SD;
    __half* d = ((job & 1) ? ploB : phiB) + (size_t)slot * MS + bz * SD;

    const int x = blockIdx.x * 64 + threadIdx.x * 2;
    const int y = blockIdx.y * 64 + threadIdx.y;
    #pragma unroll
    for (int j = 0; j < 64; j += 8) {
        __half2 v = *(const __half2*)(s + (size_t)(y + j) * 1024 + x);
        t[threadIdx.y + j][threadIdx.x * 2]     = __low2half(v);
        t[threadIdx.y + j][threadIdx.x * 2 + 1] = __high2half(v);
    }
    __syncthreads();
    const int xo = blockIdx.y * 64 + threadIdx.x * 2;
    const int yo = blockIdx.x * 64 + threadIdx.y;
    #pragma unroll
    for (int j = 0; j < 64; j += 8) {
        __half2 v = __halves2half2(
            t[threadIdx.x * 2][threadIdx.y + j],
            t[threadIdx.x * 2 + 1][threadIdx.y + j]);
        *(__half2*)(d + (size_t)(yo + j) * 1024 + xo) = v;
    }
}

// ---------------------------------------------------------------------------
// GEMM core config (identical to the validated R11 kernel)
// ---------------------------------------------------------------------------
#define RS 40                     // smem row stride in halves (80B)
#define OPBYTES (128*RS*2)        // 10240 per operand per stage
#define NSTAGE 3
#define GSMEM (NSTAGE*2*OPBYTES)  // 61440

struct SegPtrs { const __half* a[6]; const __half* b[6]; };

// Shared mainloop macro-free core used by all three GEMM kernels below is
// expressed as a repeated pattern (kept inline in each kernel for clarity).

// ---------------------------------------------------------------------------
// Merged projection GEMM: z = j (0..5). For each j:
//   segs: cross {x_lo.w_hi, x_hi.w_lo} (f16 acc), main {x_hi.w_hi} (f32 acc)
//   epilogue: + bias -> split fp16 hi/lo planes (temp slots for j=2,4,5)
// ---------------------------------------------------------------------------
__global__ __launch_bounds__(256, 2)
void proj_gemm(const __half* __restrict__ xhi, const __half* __restrict__ xlo,
               const __half* __restrict__ whi, const __half* __restrict__ wlo,
               Ptr6 bv,
               __half* __restrict__ phiB, __half* __restrict__ ploB,
               __half* __restrict__ thiB, __half* __restrict__ tloB)
{
    extern __shared__ __align__(128) char sm[];
    __shared__ const __half* sAp[3];
    __shared__ const __half* sBp[3];

    const int tid = threadIdx.x;
    const int m0 = blockIdx.y * 128;
    const int n0 = blockIdx.x * 128;
    const int j = blockIdx.z;

    if (tid < 3) {
        const __half* aseg = (tid == 0) ? (xlo + (size_t)j * MS)
                                        : (xhi + (size_t)j * MS);
        const __half* bseg = (tid == 0) ? (whi + (size_t)j * WS)
                           : (tid == 1) ? (wlo + (size_t)j * WS)
                                        : (whi + (size_t)j * WS);
        sAp[tid] = aseg + (size_t)m0 * 1024;
        sBp[tid] = bseg + (size_t)n0 * 1024;
    }
    __syncthreads();

    const float* bias = bv.p[j];
    __half *hiP, *loP;
    if (j == 2)      { hiP = thiB + 0 * MS; loP = tloB + 0 * MS; }
    else if (j == 4) { hiP = thiB + 1 * MS; loP = tloB + 1 * MS; }
    else if (j == 5) { hiP = thiB + 2 * MS; loP = tloB + 2 * MS; }
    else             { hiP = phiB + (size_t)j * MS; loP = ploB + (size_t)j * MS; }

    const uint32_t smb = smem_u32(sm);
    const int r0 = tid >> 2, c0 = tid & 3;
    const int NITc = 2 * 32;      // 2 cross segs
    const int NIT = 3 * 32;       // + 1 main seg

    auto issue = [&](int it) {
        const int seg = it >> 5, kc = it & 31;
        const uint32_t st = smb + (uint32_t)(it % NSTAGE) * (2 * OPBYTES);
        const __half* ga = sAp[seg] + kc * 32;
        const __half* gb = sBp[seg] + kc * 32;
        cp16(st + r0 * 80 + c0 * 16,            ga + (size_t)r0 * 1024 + c0 * 8);
        cp16(st + (r0 + 64) * 80 + c0 * 16,     ga + (size_t)(r0 + 64) * 1024 + c0 * 8);
        cp16(st + OPBYTES + r0 * 80 + c0 * 16,        gb + (size_t)r0 * 1024 + c0 * 8);
        cp16(st + OPBYTES + (r0 + 64) * 80 + c0 * 16, gb + (size_t)(r0 + 64) * 1024 + c0 * 8);
    };

    const int lane = tid & 31, w = tid >> 5;
    const int wm = (w >> 1) * 32;
    const int wn = (w & 1) * 64;
    const uint32_t lmo = (uint32_t)((lane & 15) * 80 + (lane >> 4) * 16);

    issue(0);
    asm volatile("cp.async.commit_group;" ::: "memory");
    issue(1);
    asm volatile("cp.async.commit_group;" ::: "memory");

    uint32_t hacc[2][8][2];
    #pragma unroll
    for (int i = 0; i < 2; i++)
        #pragma unroll
        for (int q = 0; q < 8; q++) { hacc[i][q][0] = 0u; hacc[i][q][1] = 0u; }

    for (int it = 0; it < NITc; ++it) {
        asm volatile("cp.async.wait_group 1;" ::: "memory");
        __syncthreads();
        if (it + 2 < NIT) issue(it + 2);
        asm volatile("cp.async.commit_group;" ::: "memory");

        const uint32_t stg = smb + (uint32_t)(it % NSTAGE) * (2 * OPBYTES);
        const uint32_t sa = stg + wm * 80 + lmo;
        const uint32_t sb = stg + OPBYTES + wn * 80 + lmo;

        #pragma unroll
        for (int ks = 0; ks < 2; ks++) {
            uint32_t A0[4], A1[4], Bf[8][2];
            ldmx4(A0[0], A0[1], A0[2], A0[3], sa + ks * 32);
            ldmx4(A1[0], A1[1], A1[2], A1[3], sa + 1280 + ks * 32);
            #pragma unroll
            for (int q = 0; q < 4; q++) {
                uint32_t t0, t1, t2, t3;
                ldmx4(t0, t1, t2, t3, sb + q * 1280 + ks * 32);
                Bf[2*q][0] = t0; Bf[2*q][1] = t2;
                Bf[2*q+1][0] = t1; Bf[2*q+1][1] = t3;
            }
            #pragma unroll
            for (int nt = 0; nt < 8; nt++) {
                mma16816h(hacc[0][nt], A0, Bf[nt]);
                mma16816h(hacc[1][nt], A1, Bf[nt]);
            }
        }
    }

    float acc[2][8][4];
    #pragma unroll
    for (int i = 0; i < 2; i++)
        #pragma unroll
        for (int q = 0; q < 8; q++) {
            float2 p0 = __half22float2(*(__half2*)&hacc[i][q][0]);
            float2 p1 = __half22float2(*(__half2*)&hacc[i][q][1]);
            acc[i][q][0] = p0.x; acc[i][q][1] = p0.y;
            acc[i][q][2] = p1.x; acc[i][q][3] = p1.y;
        }

    for (int it = NITc; it < NIT; ++it) {
        asm volatile("cp.async.wait_group 1;" ::: "memory");
        __syncthreads();
        if (it + 2 < NIT) issue(it + 2);
        asm volatile("cp.async.commit_group;" ::: "memory");

        const uint32_t stg = smb + (uint32_t)(it % NSTAGE) * (2 * OPBYTES);
        const uint32_t sa = stg + wm * 80 + lmo;
        const uint32_t sb = stg + OPBYTES + wn * 80 + lmo;

        #pragma unroll
        for (int ks = 0; ks < 2; ks++) {
            uint32_t A0[4], A1[4], Bf[8][2];
            ldmx4(A0[0], A0[1], A0[2], A0[3], sa + ks * 32);
            ldmx4(A1[0], A1[1], A1[2], A1[3], sa + 1280 + ks * 32);
            #pragma unroll
            for (int q = 0; q < 4; q++) {
                uint32_t t0, t1, t2, t3;
                ldmx4(t0, t1, t2, t3, sb + q * 1280 + ks * 32);
                Bf[2*q][0] = t0; Bf[2*q][1] = t2;
                Bf[2*q+1][0] = t1; Bf[2*q+1][1] = t3;
            }
            #pragma unroll
            for (int nt = 0; nt < 8; nt++) {
                mma16816(acc[0][nt], A0, Bf[nt]);
                mma16816(acc[1][nt], A1, Bf[nt]);
            }
        }
    }

    const int g = lane >> 2, t4 = lane & 3;
    #pragma unroll
    for (int mt = 0; mt < 2; mt++) {
        #pragma unroll
        for (int nt = 0; nt < 8; nt++) {
            const int rowA = m0 + wm + mt * 16 + g;
            const int rowB = rowA + 8;
            const int col  = n0 + wn + nt * 8 + 2 * t4;
            const float b0v = bias[col], b1v = bias[col + 1];
            const float v0 = acc[mt][nt][0] + b0v, v1 = acc[mt][nt][1] + b1v;
            const float v2 = acc[mt][nt][2] + b0v, v3 = acc[mt][nt][3] + b1v;
            __half h0, h1, h2, h3; float l0, l1, l2, l3;
            fsplit(v0, h0, l0); fsplit(v1, h1, l1);
            fsplit(v2, h2, l2); fsplit(v3, h3, l3);
            *(__half2*)(hiP + (size_t)rowA * 1024 + col) = __halves2half2(h0, h1);
            *(__half2*)(hiP + (size_t)rowB * 1024 + col) = __halves2half2(h2, h3);
            *(__half2*)(loP + (size_t)rowA * 1024 + col) =
                __halves2half2(__float2half_rn(l0), __float2half_rn(l1));
            *(__half2*)(loP + (size_t)rowB * 1024 + col) =
                __halves2half2(__float2half_rn(l2), __float2half_rn(l3));
        }
    }
}

// ---------------------------------------------------------------------------
// Scores GEMM (z = batch): 4 cross segs (f16 acc) + 2 main segs (f32 acc),
// fp32*alpha epilogue. Identical math to R11.
// ---------------------------------------------------------------------------
__global__ __launch_bounds__(256, 2)
void scores_gemm(SegPtrs segs, float* __restrict__ Cf, float alpha)
{
    extern __shared__ __align__(128) char sm[];
    __shared__ const __half* sAp[6];
    __shared__ const __half* sBp[6];

    const int tid = threadIdx.x;
    const int m0 = blockIdx.y * 128;
    const int n0 = blockIdx.x * 128;
    const size_t bz = blockIdx.z;

    if (tid < 6) {
        sAp[tid] = segs.a[tid] + bz * SD + (size_t)m0 * 1024;
        sBp[tid] = segs.b[tid] + bz * SD + (size_t)n0 * 1024;
    }
    __syncthreads();

    const uint32_t smb = smem_u32(sm);
    const int r0 = tid >> 2, c0 = tid & 3;
    const int NITc = 4 * 32;
    const int NIT = 6 * 32;

    auto issue = [&](int it) {
        const int seg = it >> 5, kc = it & 31;
        const uint32_t st = smb + (uint32_t)(it % NSTAGE) * (2 * OPBYTES);
        const __half* ga = sAp[seg] + kc * 32;
        const __half* gb = sBp[seg] + kc * 32;
        cp16(st + r0 * 80 + c0 * 16,            ga + (size_t)r0 * 1024 + c0 * 8);
        cp16(st + (r0 + 64) * 80 + c0 * 16,     ga + (size_t)(r0 + 64) * 1024 + c0 * 8);
        cp16(st + OPBYTES + r0 * 80 + c0 * 16,        gb + (size_t)r0 * 1024 + c0 * 8);
        cp16(st + OPBYTES + (r0 + 64) * 80 + c0 * 16, gb + (size_t)(r0 + 64) * 1024 + c0 * 8);
    };

    const int lane = tid & 31, w = tid >> 5;
    const int wm = (w >> 1) * 32;
    const int wn = (w & 1) * 64;
    const uint32_t lmo = (uint32_t)((lane & 15) * 80 + (lane >> 4) * 16);

    issue(0);
    asm volatile("cp.async.commit_group;" ::: "memory");
    issue(1);
    asm volatile("cp.async.commit_group;" ::: "memory");

    uint32_t hacc[2][8][2];
    #pragma unroll
    for (int i = 0; i < 2; i++)
        #pragma unroll
        for (int q = 0; q < 8; q++) { hacc[i][q][0] = 0u; hacc[i][q][1] = 0u; }

    for (int it = 0; it < NITc; ++it) {
        asm volatile("cp.async.wait_group 1;" ::: "memory");
        __syncthreads();
        if (it + 2 < NIT) issue(it + 2);
        asm volatile("cp.async.commit_group;" ::: "memory");

        const uint32_t stg = smb + (uint32_t)(it % NSTAGE) * (2 * OPBYTES);
        const uint32_t sa = stg + wm * 80 + lmo;
        const uint32_t sb = stg + OPBYTES + wn * 80 + lmo;

        #pragma unroll
        for (int ks = 0; ks < 2; ks++) {
            uint32_t A0[4], A1[4], Bf[8][2];
            ldmx4(A0[0], A0[1], A0[2], A0[3], sa + ks * 32);
            ldmx4(A1[0], A1[1], A1[2], A1[3], sa + 1280 + ks * 32);
            #pragma unroll
            for (int q = 0; q < 4; q++) {
                uint32_t t0, t1, t2, t3;
                ldmx4(t0, t1, t2, t3, sb + q * 1280 + ks * 32);
                Bf[2*q][0] = t0; Bf[2*q][1] = t2;
                Bf[2*q+1][0] = t1; Bf[2*q+1][1] = t3;
            }
            #pragma unroll
            for (int nt = 0; nt < 8; nt++) {
                mma16816h(hacc[0][nt], A0, Bf[nt]);
                mma16816h(hacc[1][nt], A1, Bf[nt]);
            }
        }
    }

    float acc[2][8][4];
    #pragma unroll
    for (int i = 0; i < 2; i++)
        #pragma unroll
        for (int q = 0; q < 8; q++) {
            float2 p0 = __half22float2(*(__half2*)&hacc[i][q][0]);
            float2 p1 = __half22float2(*(__half2*)&hacc[i][q][1]);
            acc[i][q][0] = p0.x; acc[i][q][1] = p0.y;
            acc[i][q][2] = p1.x; acc[i][q][3] = p1.y;
        }

    for (int it = NITc; it < NIT; ++it) {
        asm volatile("cp.async.wait_group 1;" ::: "memory");
        __syncthreads();
        if (it + 2 < NIT) issue(it + 2);
        asm volatile("cp.async.commit_group;" ::: "memory");

        const uint32_t stg = smb + (uint32_t)(it % NSTAGE) * (2 * OPBYTES);
        const uint32_t sa = stg + wm * 80 + lmo;
        const uint32_t sb = stg + OPBYTES + wn * 80 + lmo;

        #pragma unroll
        for (int ks = 0; ks < 2; ks++) {
            uint32_t A0[4], A1[4], Bf[8][2];
            ldmx4(A0[0], A0[1], A0[2], A0[3], sa + ks * 32);
            ldmx4(A1[0], A1[1], A1[2], A1[3], sa + 1280 + ks * 32);
            #pragma unroll
            for (int q = 0; q < 4; q++) {
                uint32_t t0, t1, t2, t3;
                ldmx4(t0, t1, t2, t3, sb + q * 1280 + ks * 32);
                Bf[2*q][0] = t0; Bf[2*q][1] = t2;
                Bf[2*q+1][0] = t1; Bf[2*q+1][1] = t3;
            }
            #pragma unroll
            for (int nt = 0; nt < 8; nt++) {
                mma16816(acc[0][nt], A0, Bf[nt]);
                mma16816(acc[1][nt], A1, Bf[nt]);
            }
        }
    }

    const int g = lane >> 2, t4 = lane & 3;
    #pragma unroll
    for (int mt = 0; mt < 2; mt++) {
        #pragma unroll
        for (int nt = 0; nt < 8; nt++) {
            const int rowA = m0 + wm + mt * 16 + g;
            const int rowB = rowA + 8;
            const int col  = n0 + wn + nt * 8 + 2 * t4;
            float2 v0 = make_float2(acc[mt][nt][0] * alpha, acc[mt][nt][1] * alpha);
            float2 v1 = make_float2(acc[mt][nt][2] * alpha, acc[mt][nt][3] * alpha);
            *(float2*)(Cf + bz * SD + (size_t)rowA * 1024 + col) = v0;
            *(float2*)(Cf + bz * SD + (size_t)rowB * 1024 + col) = v1;
        }
    }
}

// ---------------------------------------------------------------------------
// Merged attn@V GEMM: z in [0,32). half = z>>4 selects (vrT->out) vs
// (viT->out+MS); bz = z&15. Segs: cross {a_lo.v_hi, a_hi.v_lo} (f16 acc),
// main {a_hi.v_hi} (f32 acc). Identical math to R11's two launches.
// ---------------------------------------------------------------------------
__global__ __launch_bounds__(256, 2)
void av_gemm(const __half* __restrict__ ahi, const __half* __restrict__ alo,
             const __half* __restrict__ phiB, const __half* __restrict__ ploB,
             float* __restrict__ outB)
{
    extern __shared__ __align__(128) char sm[];
    __shared__ const __half* sAp[3];
    __shared__ const __half* sBp[3];

    const int tid = threadIdx.x;
    const int m0 = blockIdx.y * 128;
    const int n0 = blockIdx.x * 128;
    const int z = blockIdx.z;
    const int hlf = z >> 4;
    const size_t bz = (size_t)(z & 15);

    const __half* bhi = phiB + (size_t)(hlf ? 5 : 4) * MS;
    const __half* blo = ploB + (size_t)(hlf ? 5 : 4) * MS;
    float* Cf = outB + (size_t)hlf * MS;

    if (tid < 3) {
        const __half* aseg = (tid == 0) ? alo : ahi;
        const __half* bseg = (tid == 1) ? blo : bhi;
        sAp[tid] = aseg + bz * SD + (size_t)m0 * 1024;
        sBp[tid] = bseg + bz * SD + (size_t)n0 * 1024;
    }
    __syncthreads();

    const uint32_t smb = smem_u32(sm);
    const int r0 = tid >> 2, c0 = tid & 3;
    const int NITc = 2 * 32;
    const int NIT = 3 * 32;

    auto issue = [&](int it) {
        const int seg = it >> 5, kc = it & 31;
        const uint32_t st = smb + (uint32_t)(it % NSTAGE) * (2 * OPBYTES);
        const __half* ga = sAp[seg] + kc * 32;
        const __half* gb = sBp[seg] + kc * 32;
        cp16(st + r0 * 80 + c0 * 16,            ga + (size_t)r0 * 1024 + c0 * 8);
        cp16(st + (r0 + 64) * 80 + c0 * 16,     ga + (size_t)(r0 + 64) * 1024 + c0 * 8);
        cp16(st + OPBYTES + r0 * 80 + c0 * 16,        gb + (size_t)r0 * 1024 + c0 * 8);
        cp16(st + OPBYTES + (r0 + 64) * 80 + c0 * 16, gb + (size_t)(r0 + 64) * 1024 + c0 * 8);
    };

    const int lane = tid & 31, w = tid >> 5;
    const int wm = (w >> 1) * 32;
    const int wn = (w & 1) * 64;
    const uint32_t lmo = (uint32_t)((lane & 15) * 80 + (lane >> 4) * 16);

    issue(0);
    asm volatile("cp.async.commit_group;" ::: "memory");
    issue(1);
    asm volatile("cp.async.commit_group;" ::: "memory");

    uint32_t hacc[2][8][2];
    #pragma unroll
    for (int i = 0; i < 2; i++)
        #pragma unroll
        for (int q = 0; q < 8; q++) { hacc[i][q][0] = 0u; hacc[i][q][1] = 0u; }

    for (int it = 0; it < NITc; ++it) {
        asm volatile("cp.async.wait_group 1;" ::: "memory");
        __syncthreads();
        if (it + 2 < NIT) issue(it + 2);
        asm volatile("cp.async.commit_group;" ::: "memory");

        const uint32_t stg = smb + (uint32_t)(it % NSTAGE) * (2 * OPBYTES);
        const uint32_t sa = stg + wm * 80 + lmo;
        const uint32_t sb = stg + OPBYTES + wn * 80 + lmo;

        #pragma unroll
        for (int ks = 0; ks < 2; ks++) {
            uint32_t A0[4], A1[4], Bf[8][2];
            ldmx4(A0[0], A0[1], A0[2], A0[3], sa + ks * 32);
            ldmx4(A1[0], A1[1], A1[2], A1[3], sa + 1280 + ks * 32);
            #pragma unroll
            for (int q = 0; q < 4; q++) {
                uint32_t t0, t1, t2, t3;
                ldmx4(t0, t1, t2, t3, sb + q * 1280 + ks * 32);
                Bf[2*q][0] = t0; Bf[2*q][1] = t2;
                Bf[2*q+1][0] = t1; Bf[2*q+1][1] = t3;
            }
            #pragma unroll
            for (int nt = 0; nt < 8; nt++) {
                mma16816h(hacc[0][nt], A0, Bf[nt]);
                mma16816h(hacc[1][nt], A1, Bf[nt]);
            }
        }
    }

    float acc[2][8][4];
    #pragma unroll
    for (int i = 0; i < 2; i++)
        #pragma unroll
        for (int q = 0; q < 8; q++) {
            float2 p0 = __half22float2(*(__half2*)&hacc[i][q][0]);
            float2 p1 = __half22float2(*(__half2*)&hacc[i][q][1]);
            acc[i][q][0] = p0.x; acc[i][q][1] = p0.y;
            acc[i][q][2] = p1.x; acc[i][q][3] = p1.y;
        }

    for (int it = NITc; it < NIT; ++it) {
        asm volatile("cp.async.wait_group 1;" ::: "memory");
        __syncthreads();
        if (it + 2 < NIT) issue(it + 2);
        asm volatile("cp.async.commit_group;" ::: "memory");

        const uint32_t stg = smb + (uint32_t)(it % NSTAGE) * (2 * OPBYTES);
        const uint32_t sa = stg + wm * 80 + lmo;
        const uint32_t sb = stg + OPBYTES + wn * 80 + lmo;

        #pragma unroll
        for (int ks = 0; ks < 2; ks++) {
            uint32_t A0[4], A1[4], Bf[8][2];
            ldmx4(A0[0], A0[1], A0[2], A0[3], sa + ks * 32);
            ldmx4(A1[0], A1[1], A1[2], A1[3], sa + 1280 + ks * 32);
            #pragma unroll
            for (int q = 0; q < 4; q++) {
                uint32_t t0, t1, t2, t3;
                ldmx4(t0, t1, t2, t3, sb + q * 1280 + ks * 32);
                Bf[2*q][0] = t0; Bf[2*q][1] = t2;
                Bf[2*q+1][0] = t1; Bf[2*q+1][1] = t3;
            }
            #pragma unroll
            for (int nt = 0; nt < 8; nt++) {
                mma16816(acc[0][nt], A0, Bf[nt]);
                mma16816(acc[1][nt], A1, Bf[nt]);
            }
        }
    }

    const int g = lane >> 2, t4 = lane & 3;
    #pragma unroll
    for (int mt = 0; mt < 2; mt++) {
        #pragma unroll
        for (int nt = 0; nt < 8; nt++) {
            const int rowA = m0 + wm + mt * 16 + g;
            const int rowB = rowA + 8;
            const int col  = n0 + wn + nt * 8 + 2 * t4;
            float2 v0 = make_float2(acc[mt][nt][0], acc[mt][nt][1]);
            float2 v1 = make_float2(acc[mt][nt][2], acc[mt][nt][3]);
            *(float2*)(Cf + bz * SD + (size_t)rowA * 1024 + col) = v0;
            *(float2*)(Cf + bz * SD + (size_t)rowB * 1024 + col) = v1;
        }
    }
}

// ---------------------------------------------------------------------------
// Row softmax over 1024, writes attn hi/lo fp16 planes. (R11 version)
// ---------------------------------------------------------------------------
__global__ __launch_bounds__(256)
void softmax_split(const float* __restrict__ s, __half* __restrict__ hi,
                   __half* __restrict__ lo)
{
    const size_t row = blockIdx.x;
    const float4* p = (const float4*)(s + row * 1024);
    const int tid = threadIdx.x;

    float4 v = p[tid];
    float m = fmaxf(fmaxf(v.x, v.y), fmaxf(v.z, v.w));
    #pragma unroll
    for (int o = 16; o > 0; o >>= 1)
        m = fmaxf(m, __shfl_xor_sync(0xffffffffu, m, o));

    __shared__ float red[8];
    __shared__ float fin[2];
    if ((tid & 31) == 0) red[tid >> 5] = m;
    __syncthreads();
    if (tid < 32) {
        float t = (tid < 8) ? red[tid] : -3.4e38f;
        #pragma unroll
        for (int o = 4; o > 0; o >>= 1)
            t = fmaxf(t, __shfl_xor_sync(0xffffffffu, t, o));
        if (tid == 0) fin[0] = t;
    }
    __syncthreads();
    m = fin[0];

    v.x = expf(v.x - m); v.y = expf(v.y - m);
    v.z = expf(v.z - m); v.w = expf(v.w - m);
    float sum = v.x + v.y + v.z + v.w;
    #pragma unroll
    for (int o = 16; o > 0; o >>= 1)
        sum += __shfl_xor_sync(0xffffffffu, sum, o);
    if ((tid & 31) == 0) red[tid >> 5] = sum;
    __syncthreads();
    if (tid < 32) {
        float t = (tid < 8) ? red[tid] : 0.f;
        #pragma unroll
        for (int o = 4; o > 0; o >>= 1)
            t += __shfl_xor_sync(0xffffffffu, t, o);
        if (tid == 0) fin[1] = t;
    }
    __syncthreads();
    const float inv = 1.0f / fin[1];
    v.x *= inv; v.y *= inv; v.z *= inv; v.w *= inv;

    __half h0, h1, h2, h3; float l0, l1, l2, l3;
    fsplit(v.x, h0, l0); fsplit(v.y, h1, l1);
    fsplit(v.z, h2, l2); fsplit(v.w, h3, l3);
    __half2* ph = (__half2*)(hi + row * 1024 + tid * 4);
    __half2* pl = (__half2*)(lo + row * 1024 + tid * 4);
    ph[0] = __halves2half2(h0, h1);
    ph[1] = __halves2half2(h2, h3);
    pl[0] = __halves2half2(__float2half_rn(l0), __float2half_rn(l1));
    pl[1] = __halves2half2(__float2half_rn(l2), __float2half_rn(l3));
}

// ---------------------------------------------------------------------------
// Complex LayerNorm, in place on out = [2, B*S, D].
// ---------------------------------------------------------------------------
__global__ __launch_bounds__(256)
void complex_ln_kernel(float* __restrict__ out,
                       const float* __restrict__ a2,
                       const float* __restrict__ b2)
{
    const size_t row = blockIdx.x;
    float* pr = out + row * 1024;
    float* pi = out + MS + row * 1024;
    const int tid = threadIdx.x;

    float4 zr = ((float4*)pr)[tid];
    float4 zi = ((float4*)pi)[tid];

    float sv[5];
    sv[0] = zr.x + zr.y + zr.z + zr.w;
    sv[1] = zi.x + zi.y + zi.z + zi.w;
    sv[2] = zr.x*zr.x + zr.y*zr.y + zr.z*zr.z + zr.w*zr.w;
    sv[3] = zi.x*zi.x + zi.y*zi.y + zi.z*zi.z + zi.w*zi.w;
    sv[4] = zr.x*zi.x + zr.y*zi.y + zr.z*zi.z + zr.w*zi.w;

    #pragma unroll
    for (int u = 0; u < 5; u++)
        #pragma unroll
        for (int o = 16; o > 0; o >>= 1)
            sv[u] += __shfl_xor_sync(0xffffffffu, sv[u], o);

    __shared__ float red[5][8];
    __shared__ float fin[5];
    if ((tid & 31) == 0) {
        #pragma unroll
        for (int u = 0; u < 5; u++) red[u][tid >> 5] = sv[u];
    }
    __syncthreads();
    if (tid == 0) {
        #pragma unroll
        for (int u = 0; u < 5; u++) {
            float t = 0.f;
            #pragma unroll
            for (int wv = 0; wv < 8; wv++) t += red[u][wv];
            fin[u] = t;
        }
    }
    __syncthreads();

    const float invD = 1.0f / 1024.0f;
    const float mr = fin[0] * invD;
    const float mi = fin[1] * invD;
    const float err = fin[2] * invD - mr * mr;
    const float eii = fin[3] * invD - mi * mi;
    const float eri = fin[4] * invD - mr * mi;
    const float vr = err - eii + 1e-6f;
    const float vi = 2.0f * eri;
    const float rmod = sqrtf(vr * vr + vi * vi);
    const float sre = sqrtf(fmaxf(0.5f * (rmod + vr), 0.f));
    const float sim = copysignf(sqrtf(fmaxf(0.5f * (rmod - vr), 0.f)), vi);
    const float inv = 1.0f / fmaxf(rmod, 1e-30f);

    float4 ga = ((const float4*)a2)[tid];
    float4 gb = ((const float4*)b2)[tid];

    float4 yr, yi;
    {
        float ar = zr.x - mr, ai = zi.x - mi;
        yr.x = (ar * sre + ai * sim) * inv; yi.x = (ai * sre - ar * sim) * inv;
        ar = zr.y - mr; ai = zi.y - mi;
        yr.y = (ar * sre + ai * sim) * inv; yi.y = (ai * sre - ar * sim) * inv;
        ar = zr.z - mr; ai = zi.z - mi;
        yr.z = (ar * sre + ai * sim) * inv; yi.z = (ai * sre - ar * sim) * inv;
        ar = zr.w - mr; ai = zi.w - mi;
        yr.w = (ar * sre + ai * sim) * inv; yi.w = (ai * sre - ar * sim) * inv;
    }
    yr.x = ga.x * yr.x + gb.x; yi.x = ga.x * yi.x;
    yr.y = ga.y * yr.y + gb.y; yi.y = ga.y * yi.y;
    yr.z = ga.z * yr.z + gb.z; yi.z = ga.z * yi.z;
    yr.w = ga.w * yr.w + gb.w; yi.w = ga.w * yi.w;

    ((float4*)pr)[tid] = yr;
    ((float4*)pi)[tid] = yi;
}

// ---------------------------------------------------------------------------
extern "C" void kernel_launch(void* const* d_in, const int* in_sizes, int n_in,
                              void* d_out, int out_size)
{
    const float* a2 = (const float*)d_in[18];
    const float* b2 = (const float*)d_in[19];
    float* out = (float*)d_out;

    __half *xhi, *xlo, *whi, *wlo, *phi, *plo, *thi, *tlo, *ahi, *alo;
    float* scores;
    cudaGetSymbolAddress((void**)&xhi, g_xhi);
    cudaGetSymbolAddress((void**)&xlo, g_xlo);
    cudaGetSymbolAddress((void**)&whi, g_whi);
    cudaGetSymbolAddress((void**)&wlo, g_wlo);
    cudaGetSymbolAddress((void**)&phi, g_phi);
    cudaGetSymbolAddress((void**)&plo, g_plo);
    cudaGetSymbolAddress((void**)&thi, g_thi);
    cudaGetSymbolAddress((void**)&tlo, g_tlo);
    cudaGetSymbolAddress((void**)&ahi, g_ahi);
    cudaGetSymbolAddress((void**)&alo, g_alo);
    cudaGetSymbolAddress((void**)&scores, g_scores);

    cudaFuncSetAttribute(proj_gemm,
        cudaFuncAttributeMaxDynamicSharedMemorySize, GSMEM);
    cudaFuncSetAttribute(scores_gemm,
        cudaFuncAttributeMaxDynamicSharedMemorySize, GSMEM);
    cudaFuncSetAttribute(av_gemm,
        cudaFuncAttributeMaxDynamicSharedMemorySize, GSMEM);

    // 1) split X (6 tensors) and W (6 tensors), one launch each
    {
        Ptr6 xin{}, win{};
        for (int j = 0; j < 6; j++) xin.p[j] = (const float*)d_in[j];
        for (int j = 0; j < 6; j++) win.p[j] = (const float*)d_in[6 + 2*j];
        conv_split6<<<dim3((unsigned)(MS/4/256), 1, 6), 256>>>(
            xin, (__half2*)xhi, (__half2*)xlo, MS/4, MS/4);
        conv_split6<<<dim3((unsigned)(WS/4/256), 1, 6), 256>>>(
            win, (__half2*)whi, (__half2*)wlo, WS/4, WS/4);
    }

    // 2) all six projections in ONE launch (z = j)
    {
        Ptr6 bv{};
        for (int j = 0; j < 6; j++) bv.p[j] = (const float*)d_in[7 + 2*j];
        proj_gemm<<<dim3(8, 128, 6), 256, GSMEM>>>(
            xhi, xlo, whi, wlo, bv, phi, plo, thi, tlo);
    }

    // 2b) all six transposes in ONE launch (z = job*16 + batch)
    transpose6<<<dim3(16, 16, 96), dim3(32, 8)>>>(thi, tlo, phi, plo);

    // 3) scores = (qr@krT^T + qi@ki^T)/8: 4 cross (f16 acc) + 2 main (f32)
    {
        SegPtrs sp{};
        sp.a[0] = plo + 0*MS; sp.b[0] = phi + 2*MS;
        sp.a[1] = phi + 0*MS; sp.b[1] = plo + 2*MS;
        sp.a[2] = plo + 1*MS; sp.b[2] = phi + 3*MS;
        sp.a[3] = phi + 1*MS; sp.b[3] = plo + 3*MS;
        sp.a[4] = phi + 0*MS; sp.b[4] = phi + 2*MS;
        sp.a[5] = phi + 1*MS; sp.b[5] = phi + 3*MS;
        scores_gemm<<<dim3(8, 8, BATCH), 256, GSMEM>>>(sp, scores, 0.125f);
    }

    // 4) softmax -> attn hi/lo planes
    softmax_split<<<MTOT, 256>>>(scores, ahi, alo);

    // 5) both attn@V GEMMs in ONE launch (z = half*16 + batch)
    av_gemm<<<dim3(8, 8, 32), 256, GSMEM>>>(ahi, alo, phi, plo, out);

    // 6) complex LayerNorm in place on d_out
    complex_ln_kernel<<<MTOT, 256>>>(out, a2, b2);
}

// round 17
// speedup vs baseline: 1.3721x; 1.0255x over previous
#include <cuda_runtime.h>
#include <cuda_fp16.h>
#include <math.h>
#include <stdint.h>

// Problem constants
#define BATCH 16
#define SEQ   1024
#define DIM   1024
#define MTOT  (BATCH*SEQ)            // 16384
#define MS    ((size_t)MTOT*DIM)     // 16777216
#define SD    ((size_t)SEQ*DIM)      // per-batch stride
#define WS    ((size_t)DIM*DIM)

// fp16 hi/lo planes (device globals; cudaMalloc forbidden)
__device__ __half g_xhi[6*MS], g_xlo[6*MS];
__device__ __half g_whi[6*WS], g_wlo[6*WS];
// proj planes, slots: 0 qr, 1 qi, 2 krT, 3 ki, 4 vr, 5 vi (vr/vi untransposed)
__device__ __half g_phi[6*MS], g_plo[6*MS];
// temp (untransposed) planes for kr only
__device__ __half g_thi[MS], g_tlo[MS];
__device__ __half g_ahi[MS],  g_alo[MS];
__device__ float g_scores[(size_t)BATCH*SEQ*SEQ];

struct Ptr6  { const float* p[6]; };

// ---------------------------------------------------------------------------
// helpers
// ---------------------------------------------------------------------------
__device__ __forceinline__ uint32_t smem_u32(const void* p) {
    uint32_t r;
    asm("{ .reg .u64 t; cvta.to.shared.u64 t, %1; cvt.u32.u64 %0, t; }"
        : "=r"(r) : "l"(p));
    return r;
}

__device__ __forceinline__ void cp16(uint32_t d, const void* s) {
    asm volatile("cp.async.cg.shared.global [%0], [%1], 16;" :: "r"(d), "l"(s));
}

__device__ __forceinline__ void ldmx4(uint32_t& r0, uint32_t& r1,
                                      uint32_t& r2, uint32_t& r3, uint32_t a) {
    asm volatile("ldmatrix.sync.aligned.m8n8.x4.shared.b16 {%0,%1,%2,%3}, [%4];"
                 : "=r"(r0), "=r"(r1), "=r"(r2), "=r"(r3) : "r"(a));
}

__device__ __forceinline__ void ldmx4t(uint32_t& r0, uint32_t& r1,
                                       uint32_t& r2, uint32_t& r3, uint32_t a) {
    asm volatile("ldmatrix.sync.aligned.m8n8.x4.trans.shared.b16 {%0,%1,%2,%3}, [%4];"
                 : "=r"(r0), "=r"(r1), "=r"(r2), "=r"(r3) : "r"(a));
}

// fp16 x fp16 -> f32 accumulate
__device__ __forceinline__ void mma16816(float* c, const uint32_t* a,
                                         const uint32_t* b) {
    asm volatile(
        "mma.sync.aligned.m16n8k16.row.col.f32.f16.f16.f32 "
        "{%0,%1,%2,%3}, {%4,%5,%6,%7}, {%8,%9}, {%0,%1,%2,%3};"
        : "+f"(c[0]), "+f"(c[1]), "+f"(c[2]), "+f"(c[3])
        : "r"(a[0]), "r"(a[1]), "r"(a[2]), "r"(a[3]), "r"(b[0]), "r"(b[1]));
}

// fp16 x fp16 -> f16 accumulate — small cross terms only
__device__ __forceinline__ void mma16816h(uint32_t* c, const uint32_t* a,
                                          const uint32_t* b) {
    asm volatile(
        "mma.sync.aligned.m16n8k16.row.col.f16.f16.f16.f16 "
        "{%0,%1}, {%2,%3,%4,%5}, {%6,%7}, {%0,%1};"
        : "+r"(c[0]), "+r"(c[1])
        : "r"(a[0]), "r"(a[1]), "r"(a[2]), "r"(a[3]), "r"(b[0]), "r"(b[1]));
}

__device__ __forceinline__ void fsplit(float x, __half& h, float& l) {
    h = __float2half_rn(x);
    l = x - __half2float(h);
}

// ---------------------------------------------------------------------------
// fp32 -> (hi, lo) fp16 planes, 6 tensors in one launch (z = tensor index)
// ---------------------------------------------------------------------------
__global__ __launch_bounds__(256)
void conv_split6(Ptr6 in, __half2* __restrict__ hiBase,
                 __half2* __restrict__ loBase, size_t plane4, size_t n4)
{
    const int j = blockIdx.z;
    size_t i = (size_t)blockIdx.x * 256 + threadIdx.x;
    if (i >= n4) return;
    const float4* src = (const float4*)in.p[j];
    __half2* hi = hiBase + j * plane4 * 2;
    __half2* lo = loBase + j * plane4 * 2;
    float4 v = src[i];
    __half h0, h1, h2, h3; float l0, l1, l2, l3;
    fsplit(v.x, h0, l0); fsplit(v.y, h1, l1);
    fsplit(v.z, h2, l2); fsplit(v.w, h3, l3);
    hi[2*i]   = __halves2half2(h0, h1);
    hi[2*i+1] = __halves2half2(h2, h3);
    lo[2*i]   = __halves2half2(__float2half_rn(l0), __float2half_rn(l1));
    lo[2*i+1] = __halves2half2(__float2half_rn(l2), __float2half_rn(l3));
}

// ---------------------------------------------------------------------------
// Coalesced per-batch 1024x1024 fp16 transpose; kr hi/lo only.
// z = job*16 + batch; job 0: thi->phi[2], job 1: tlo->plo[2]
// ---------------------------------------------------------------------------
__global__ __launch_bounds__(256)
void transpose2(const __half* __restrict__ thiB, const __half* __restrict__ tloB,
                __half* __restrict__ phiB, __half* __restrict__ ploB)
{
    __shared__ __half t[64][66];
    const int z = blockIdx.z;
    const int job = z >> 4;
    const size_t bz = z & 15;
    const __half* s = (job ? tloB : thiB) + bz * SD;
    __half* d = (job ? ploB : phiB) + (size_t)2 * MS + bz * SD;

    const int x = blockIdx.x * 64 + threadIdx.x * 2;
    const int y = blockIdx.y * 64 + threadIdx.y;
    #pragma unroll
    for (int j = 0; j < 64; j += 8) {
        __half2 v = *(const __half2*)(s + (size_t)(y + j) * 1024 + x);
        t[threadIdx.y + j][threadIdx.x * 2]     = __low2half(v);
        t[threadIdx.y + j][threadIdx.x * 2 + 1] = __high2half(v);
    }
    __syncthreads();
    const int xo = blockIdx.y * 64 + threadIdx.x * 2;
    const int yo = blockIdx.x * 64 + threadIdx.y;
    #pragma unroll
    for (int j = 0; j < 64; j += 8) {
        __half2 v = __halves2half2(
            t[threadIdx.x * 2][threadIdx.y + j],
            t[threadIdx.x * 2 + 1][threadIdx.y + j]);
        *(__half2*)(d + (size_t)(yo + j) * 1024 + xo) = v;
    }
}

// ---------------------------------------------------------------------------
// GEMM core config
// ---------------------------------------------------------------------------
#define RS 40                     // K-major smem row stride in halves (80B)
#define OPBYTES (128*RS*2)        // 10240 per K-major operand per stage
#define NSTAGE 3
#define GSMEM (NSTAGE*2*OPBYTES)  // 61440 (proj/scores kernels)

// trans-B layout for av_gemm: B tile 32 k-rows x 256B payload + 16B pad
#define OPBT   (32*272)           // 8704
#define STAGE_AV (OPBYTES + OPBT) // 18944
#define GSMEM_AV (NSTAGE*STAGE_AV)// 56832

struct SegPtrs { const __half* a[6]; const __half* b[6]; };

// ---------------------------------------------------------------------------
// Merged projection GEMM: z = j (0..5). vr/vi (j=4,5) write DIRECT final
// planes (trans-B av consumes them untransposed); only kr (j=2) to temp.
// ---------------------------------------------------------------------------
__global__ __launch_bounds__(256, 2)
void proj_gemm(const __half* __restrict__ xhi, const __half* __restrict__ xlo,
               const __half* __restrict__ whi, const __half* __restrict__ wlo,
               Ptr6 bv,
               __half* __restrict__ phiB, __half* __restrict__ ploB,
               __half* __restrict__ thiB, __half* __restrict__ tloB)
{
    extern __shared__ __align__(128) char sm[];
    __shared__ const __half* sAp[3];
    __shared__ const __half* sBp[3];

    const int tid = threadIdx.x;
    const int m0 = blockIdx.y * 128;
    const int n0 = blockIdx.x * 128;
    const int j = blockIdx.z;

    if (tid < 3) {
        const __half* aseg = (tid == 0) ? (xlo + (size_t)j * MS)
                                        : (xhi + (size_t)j * MS);
        const __half* bseg = (tid == 0) ? (whi + (size_t)j * WS)
                           : (tid == 1) ? (wlo + (size_t)j * WS)
                                        : (whi + (size_t)j * WS);
        sAp[tid] = aseg + (size_t)m0 * 1024;
        sBp[tid] = bseg + (size_t)n0 * 1024;
    }
    __syncthreads();

    const float* bias = bv.p[j];
    __half *hiP, *loP;
    if (j == 2) { hiP = thiB; loP = tloB; }
    else        { hiP = phiB + (size_t)j * MS; loP = ploB + (size_t)j * MS; }

    const uint32_t smb = smem_u32(sm);
    const int r0 = tid >> 2, c0 = tid & 3;
    const int NITc = 2 * 32;
    const int NIT = 3 * 32;

    auto issue = [&](int it) {
        const int seg = it >> 5, kc = it & 31;
        const uint32_t st = smb + (uint32_t)(it % NSTAGE) * (2 * OPBYTES);
        const __half* ga = sAp[seg] + kc * 32;
        const __half* gb = sBp[seg] + kc * 32;
        cp16(st + r0 * 80 + c0 * 16,            ga + (size_t)r0 * 1024 + c0 * 8);
        cp16(st + (r0 + 64) * 80 + c0 * 16,     ga + (size_t)(r0 + 64) * 1024 + c0 * 8);
        cp16(st + OPBYTES + r0 * 80 + c0 * 16,        gb + (size_t)r0 * 1024 + c0 * 8);
        cp16(st + OPBYTES + (r0 + 64) * 80 + c0 * 16, gb + (size_t)(r0 + 64) * 1024 + c0 * 8);
    };

    const int lane = tid & 31, w = tid >> 5;
    const int wm = (w >> 1) * 32;
    const int wn = (w & 1) * 64;
    const uint32_t lmo = (uint32_t)((lane & 15) * 80 + (lane >> 4) * 16);

    issue(0);
    asm volatile("cp.async.commit_group;" ::: "memory");
    issue(1);
    asm volatile("cp.async.commit_group;" ::: "memory");

    uint32_t hacc[2][8][2];
    #pragma unroll
    for (int i = 0; i < 2; i++)
        #pragma unroll
        for (int q = 0; q < 8; q++) { hacc[i][q][0] = 0u; hacc[i][q][1] = 0u; }

    for (int it = 0; it < NITc; ++it) {
        asm volatile("cp.async.wait_group 1;" ::: "memory");
        __syncthreads();
        if (it + 2 < NIT) issue(it + 2);
        asm volatile("cp.async.commit_group;" ::: "memory");

        const uint32_t stg = smb + (uint32_t)(it % NSTAGE) * (2 * OPBYTES);
        const uint32_t sa = stg + wm * 80 + lmo;
        const uint32_t sb = stg + OPBYTES + wn * 80 + lmo;

        #pragma unroll
        for (int ks = 0; ks < 2; ks++) {
            uint32_t A0[4], A1[4], Bf[8][2];
            ldmx4(A0[0], A0[1], A0[2], A0[3], sa + ks * 32);
            ldmx4(A1[0], A1[1], A1[2], A1[3], sa + 1280 + ks * 32);
            #pragma unroll
            for (int q = 0; q < 4; q++) {
                uint32_t t0, t1, t2, t3;
                ldmx4(t0, t1, t2, t3, sb + q * 1280 + ks * 32);
                Bf[2*q][0] = t0; Bf[2*q][1] = t2;
                Bf[2*q+1][0] = t1; Bf[2*q+1][1] = t3;
            }
            #pragma unroll
            for (int nt = 0; nt < 8; nt++) {
                mma16816h(hacc[0][nt], A0, Bf[nt]);
                mma16816h(hacc[1][nt], A1, Bf[nt]);
            }
        }
    }

    float acc[2][8][4];
    #pragma unroll
    for (int i = 0; i < 2; i++)
        #pragma unroll
        for (int q = 0; q < 8; q++) {
            float2 p0 = __half22float2(*(__half2*)&hacc[i][q][0]);
            float2 p1 = __half22float2(*(__half2*)&hacc[i][q][1]);
            acc[i][q][0] = p0.x; acc[i][q][1] = p0.y;
            acc[i][q][2] = p1.x; acc[i][q][3] = p1.y;
        }

    for (int it = NITc; it < NIT; ++it) {
        asm volatile("cp.async.wait_group 1;" ::: "memory");
        __syncthreads();
        if (it + 2 < NIT) issue(it + 2);
        asm volatile("cp.async.commit_group;" ::: "memory");

        const uint32_t stg = smb + (uint32_t)(it % NSTAGE) * (2 * OPBYTES);
        const uint32_t sa = stg + wm * 80 + lmo;
        const uint32_t sb = stg + OPBYTES + wn * 80 + lmo;

        #pragma unroll
        for (int ks = 0; ks < 2; ks++) {
            uint32_t A0[4], A1[4], Bf[8][2];
            ldmx4(A0[0], A0[1], A0[2], A0[3], sa + ks * 32);
            ldmx4(A1[0], A1[1], A1[2], A1[3], sa + 1280 + ks * 32);
            #pragma unroll
            for (int q = 0; q < 4; q++) {
                uint32_t t0, t1, t2, t3;
                ldmx4(t0, t1, t2, t3, sb + q * 1280 + ks * 32);
                Bf[2*q][0] = t0; Bf[2*q][1] = t2;
                Bf[2*q+1][0] = t1; Bf[2*q+1][1] = t3;
            }
            #pragma unroll
            for (int nt = 0; nt < 8; nt++) {
                mma16816(acc[0][nt], A0, Bf[nt]);
                mma16816(acc[1][nt], A1, Bf[nt]);
            }
        }
    }

    const int g = lane >> 2, t4 = lane & 3;
    #pragma unroll
    for (int mt = 0; mt < 2; mt++) {
        #pragma unroll
        for (int nt = 0; nt < 8; nt++) {
            const int rowA = m0 + wm + mt * 16 + g;
            const int rowB = rowA + 8;
            const int col  = n0 + wn + nt * 8 + 2 * t4;
            const float b0v = bias[col], b1v = bias[col + 1];
            const float v0 = acc[mt][nt][0] + b0v, v1 = acc[mt][nt][1] + b1v;
            const float v2 = acc[mt][nt][2] + b0v, v3 = acc[mt][nt][3] + b1v;
            __half h0, h1, h2, h3; float l0, l1, l2, l3;
            fsplit(v0, h0, l0); fsplit(v1, h1, l1);
            fsplit(v2, h2, l2); fsplit(v3, h3, l3);
            *(__half2*)(hiP + (size_t)rowA * 1024 + col) = __halves2half2(h0, h1);
            *(__half2*)(hiP + (size_t)rowB * 1024 + col) = __halves2half2(h2, h3);
            *(__half2*)(loP + (size_t)rowA * 1024 + col) =
                __halves2half2(__float2half_rn(l0), __float2half_rn(l1));
            *(__half2*)(loP + (size_t)rowB * 1024 + col) =
                __halves2half2(__float2half_rn(l2), __float2half_rn(l3));
        }
    }
}

// ---------------------------------------------------------------------------
// Scores GEMM (z = batch): 4 cross (f16 acc) + 2 main (f32 acc).
// ---------------------------------------------------------------------------
__global__ __launch_bounds__(256, 2)
void scores_gemm(SegPtrs segs, float* __restrict__ Cf, float alpha)
{
    extern __shared__ __align__(128) char sm[];
    __shared__ const __half* sAp[6];
    __shared__ const __half* sBp[6];

    const int tid = threadIdx.x;
    const int m0 = blockIdx.y * 128;
    const int n0 = blockIdx.x * 128;
    const size_t bz = blockIdx.z;

    if (tid < 6) {
        sAp[tid] = segs.a[tid] + bz * SD + (size_t)m0 * 1024;
        sBp[tid] = segs.b[tid] + bz * SD + (size_t)n0 * 1024;
    }
    __syncthreads();

    const uint32_t smb = smem_u32(sm);
    const int r0 = tid >> 2, c0 = tid & 3;
    const int NITc = 4 * 32;
    const int NIT = 6 * 32;

    auto issue = [&](int it) {
        const int seg = it >> 5, kc = it & 31;
        const uint32_t st = smb + (uint32_t)(it % NSTAGE) * (2 * OPBYTES);
        const __half* ga = sAp[seg] + kc * 32;
        const __half* gb = sBp[seg] + kc * 32;
        cp16(st + r0 * 80 + c0 * 16,            ga + (size_t)r0 * 1024 + c0 * 8);
        cp16(st + (r0 + 64) * 80 + c0 * 16,     ga + (size_t)(r0 + 64) * 1024 + c0 * 8);
        cp16(st + OPBYTES + r0 * 80 + c0 * 16,        gb + (size_t)r0 * 1024 + c0 * 8);
        cp16(st + OPBYTES + (r0 + 64) * 80 + c0 * 16, gb + (size_t)(r0 + 64) * 1024 + c0 * 8);
    };

    const int lane = tid & 31, w = tid >> 5;
    const int wm = (w >> 1) * 32;
    const int wn = (w & 1) * 64;
    const uint32_t lmo = (uint32_t)((lane & 15) * 80 + (lane >> 4) * 16);

    issue(0);
    asm volatile("cp.async.commit_group;" ::: "memory");
    issue(1);
    asm volatile("cp.async.commit_group;" ::: "memory");

    uint32_t hacc[2][8][2];
    #pragma unroll
    for (int i = 0; i < 2; i++)
        #pragma unroll
        for (int q = 0; q < 8; q++) { hacc[i][q][0] = 0u; hacc[i][q][1] = 0u; }

    for (int it = 0; it < NITc; ++it) {
        asm volatile("cp.async.wait_group 1;" ::: "memory");
        __syncthreads();
        if (it + 2 < NIT) issue(it + 2);
        asm volatile("cp.async.commit_group;" ::: "memory");

        const uint32_t stg = smb + (uint32_t)(it % NSTAGE) * (2 * OPBYTES);
        const uint32_t sa = stg + wm * 80 + lmo;
        const uint32_t sb = stg + OPBYTES + wn * 80 + lmo;

        #pragma unroll
        for (int ks = 0; ks < 2; ks++) {
            uint32_t A0[4], A1[4], Bf[8][2];
            ldmx4(A0[0], A0[1], A0[2], A0[3], sa + ks * 32);
            ldmx4(A1[0], A1[1], A1[2], A1[3], sa + 1280 + ks * 32);
            #pragma unroll
            for (int q = 0; q < 4; q++) {
                uint32_t t0, t1, t2, t3;
                ldmx4(t0, t1, t2, t3, sb + q * 1280 + ks * 32);
                Bf[2*q][0] = t0; Bf[2*q][1] = t2;
                Bf[2*q+1][0] = t1; Bf[2*q+1][1] = t3;
            }
            #pragma unroll
            for (int nt = 0; nt < 8; nt++) {
                mma16816h(hacc[0][nt], A0, Bf[nt]);
                mma16816h(hacc[1][nt], A1, Bf[nt]);
            }
        }
    }

    float acc[2][8][4];
    #pragma unroll
    for (int i = 0; i < 2; i++)
        #pragma unroll
        for (int q = 0; q < 8; q++) {
            float2 p0 = __half22float2(*(__half2*)&hacc[i][q][0]);
            float2 p1 = __half22float2(*(__half2*)&hacc[i][q][1]);
            acc[i][q][0] = p0.x; acc[i][q][1] = p0.y;
            acc[i][q][2] = p1.x; acc[i][q][3] = p1.y;
        }

    for (int it = NITc; it < NIT; ++it) {
        asm volatile("cp.async.wait_group 1;" ::: "memory");
        __syncthreads();
        if (it + 2 < NIT) issue(it + 2);
        asm volatile("cp.async.commit_group;" ::: "memory");

        const uint32_t stg = smb + (uint32_t)(it % NSTAGE) * (2 * OPBYTES);
        const uint32_t sa = stg + wm * 80 + lmo;
        const uint32_t sb = stg + OPBYTES + wn * 80 + lmo;

        #pragma unroll
        for (int ks = 0; ks < 2; ks++) {
            uint32_t A0[4], A1[4], Bf[8][2];
            ldmx4(A0[0], A0[1], A0[2], A0[3], sa + ks * 32);
            ldmx4(A1[0], A1[1], A1[2], A1[3], sa + 1280 + ks * 32);
            #pragma unroll
            for (int q = 0; q < 4; q++) {
                uint32_t t0, t1, t2, t3;
                ldmx4(t0, t1, t2, t3, sb + q * 1280 + ks * 32);
                Bf[2*q][0] = t0; Bf[2*q][1] = t2;
                Bf[2*q+1][0] = t1; Bf[2*q+1][1] = t3;
            }
            #pragma unroll
            for (int nt = 0; nt < 8; nt++) {
                mma16816(acc[0][nt], A0, Bf[nt]);
                mma16816(acc[1][nt], A1, Bf[nt]);
            }
        }
    }

    const int g = lane >> 2, t4 = lane & 3;
    #pragma unroll
    for (int mt = 0; mt < 2; mt++) {
        #pragma unroll
        for (int nt = 0; nt < 8; nt++) {
            const int rowA = m0 + wm + mt * 16 + g;
            const int rowB = rowA + 8;
            const int col  = n0 + wn + nt * 8 + 2 * t4;
            float2 v0 = make_float2(acc[mt][nt][0] * alpha, acc[mt][nt][1] * alpha);
            float2 v1 = make_float2(acc[mt][nt][2] * alpha, acc[mt][nt][3] * alpha);
            *(float2*)(Cf + bz * SD + (size_t)rowA * 1024 + col) = v0;
            *(float2*)(Cf + bz * SD + (size_t)rowB * 1024 + col) = v1;
        }
    }
}

// ---------------------------------------------------------------------------
// Merged attn@V GEMM, trans-B: B = v planes [token k, feature n] row-major,
// consumed via ldmatrix.trans (no pre-transpose). z in [0,32): hlf = z>>4
// selects (vr->out) vs (vi->out+MS); bz = z&15. Same values, same k-order
// as the R15 baseline -> bit-identical results expected.
// ---------------------------------------------------------------------------
__global__ __launch_bounds__(256, 2)
void av_gemm(const __half* __restrict__ ahi, const __half* __restrict__ alo,
             const __half* __restrict__ phiB, const __half* __restrict__ ploB,
             float* __restrict__ outB)
{
    extern __shared__ __align__(128) char sm[];
    __shared__ const __half* sAp[3];
    __shared__ const __half* sBp[3];

    const int tid = threadIdx.x;
    const int m0 = blockIdx.y * 128;
    const int n0 = blockIdx.x * 128;
    const int z = blockIdx.z;
    const int hlf = z >> 4;
    const size_t bz = (size_t)(z & 15);

    const __half* bhi = phiB + (size_t)(hlf ? 5 : 4) * MS;
    const __half* blo = ploB + (size_t)(hlf ? 5 : 4) * MS;
    float* Cf = outB + (size_t)hlf * MS;

    if (tid < 3) {
        const __half* aseg = (tid == 0) ? alo : ahi;
        const __half* bseg = (tid == 1) ? blo : bhi;
        sAp[tid] = aseg + bz * SD + (size_t)m0 * 1024;
        sBp[tid] = bseg + bz * SD + n0;        // rows advance over tokens (k)
    }
    __syncthreads();

    const uint32_t smb = smem_u32(sm);
    const int r0 = tid >> 2, c0 = tid & 3;     // A loader mapping
    const int rb = tid >> 4, sb8 = tid & 15;   // B loader: 16 rows x 16 segs
    const int NITc = 2 * 32;
    const int NIT = 3 * 32;

    auto issue = [&](int it) {
        const int seg = it >> 5, kc = it & 31;
        const uint32_t st = smb + (uint32_t)(it % NSTAGE) * STAGE_AV;
        const __half* ga = sAp[seg] + kc * 32;
        cp16(st + r0 * 80 + c0 * 16,        ga + (size_t)r0 * 1024 + c0 * 8);
        cp16(st + (r0 + 64) * 80 + c0 * 16, ga + (size_t)(r0 + 64) * 1024 + c0 * 8);
        const __half* gb = sBp[seg] + (size_t)(kc * 32) * 1024;
        cp16(st + OPBYTES + rb * 272 + sb8 * 16,
             gb + (size_t)rb * 1024 + sb8 * 8);
        cp16(st + OPBYTES + (rb + 16) * 272 + sb8 * 16,
             gb + (size_t)(rb + 16) * 1024 + sb8 * 8);
    };

    const int lane = tid & 31, w = tid >> 5;
    const int wm = (w >> 1) * 32;
    const int wn = (w & 1) * 64;
    const uint32_t lmo = (uint32_t)((lane & 15) * 80 + (lane >> 4) * 16);
    // trans-B lane address: row = k (lane&15) within 16-row half, byte col =
    // warp n-offset*2 + (lane>>4)*16; q adds 32B, ks adds 16 rows (16*272B).
    const uint32_t lmoB = (uint32_t)((lane & 15) * 272 + (lane >> 4) * 16
                                     + wn * 2);

    issue(0);
    asm volatile("cp.async.commit_group;" ::: "memory");
    issue(1);
    asm volatile("cp.async.commit_group;" ::: "memory");

    uint32_t hacc[2][8][2];
    #pragma unroll
    for (int i = 0; i < 2; i++)
        #pragma unroll
        for (int q = 0; q < 8; q++) { hacc[i][q][0] = 0u; hacc[i][q][1] = 0u; }

    for (int it = 0; it < NITc; ++it) {
        asm volatile("cp.async.wait_group 1;" ::: "memory");
        __syncthreads();
        if (it + 2 < NIT) issue(it + 2);
        asm volatile("cp.async.commit_group;" ::: "memory");

        const uint32_t stg = smb + (uint32_t)(it % NSTAGE) * STAGE_AV;
        const uint32_t sa = stg + wm * 80 + lmo;
        const uint32_t sbb = stg + OPBYTES + lmoB;

        #pragma unroll
        for (int ks = 0; ks < 2; ks++) {
            uint32_t A0[4], A1[4], Bf[8][2];
            ldmx4(A0[0], A0[1], A0[2], A0[3], sa + ks * 32);
            ldmx4(A1[0], A1[1], A1[2], A1[3], sa + 1280 + ks * 32);
            #pragma unroll
            for (int q = 0; q < 4; q++) {
                uint32_t t0, t1, t2, t3;
                ldmx4t(t0, t1, t2, t3, sbb + ks * (16 * 272) + q * 32);
                Bf[2*q][0] = t0; Bf[2*q][1] = t1;
                Bf[2*q+1][0] = t2; Bf[2*q+1][1] = t3;
            }
            #pragma unroll
            for (int nt = 0; nt < 8; nt++) {
                mma16816h(hacc[0][nt], A0, Bf[nt]);
                mma16816h(hacc[1][nt], A1, Bf[nt]);
            }
        }
    }

    float acc[2][8][4];
    #pragma unroll
    for (int i = 0; i < 2; i++)
        #pragma unroll
        for (int q = 0; q < 8; q++) {
            float2 p0 = __half22float2(*(__half2*)&hacc[i][q][0]);
            float2 p1 = __half22float2(*(__half2*)&hacc[i][q][1]);
            acc[i][q][0] = p0.x; acc[i][q][1] = p0.y;
            acc[i][q][2] = p1.x; acc[i][q][3] = p1.y;
        }

    for (int it = NITc; it < NIT; ++it) {
        asm volatile("cp.async.wait_group 1;" ::: "memory");
        __syncthreads();
        if (it + 2 < NIT) issue(it + 2);
        asm volatile("cp.async.commit_group;" ::: "memory");

        const uint32_t stg = smb + (uint32_t)(it % NSTAGE) * STAGE_AV;
        const uint32_t sa = stg + wm * 80 + lmo;
        const uint32_t sbb = stg + OPBYTES + lmoB;

        #pragma unroll
        for (int ks = 0; ks < 2; ks++) {
            uint32_t A0[4], A1[4], Bf[8][2];
            ldmx4(A0[0], A0[1], A0[2], A0[3], sa + ks * 32);
            ldmx4(A1[0], A1[1], A1[2], A1[3], sa + 1280 + ks * 32);
            #pragma unroll
            for (int q = 0; q < 4; q++) {
                uint32_t t0, t1, t2, t3;
                ldmx4t(t0, t1, t2, t3, sbb + ks * (16 * 272) + q * 32);
                Bf[2*q][0] = t0; Bf[2*q][1] = t1;
                Bf[2*q+1][0] = t2; Bf[2*q+1][1] = t3;
            }
            #pragma unroll
            for (int nt = 0; nt < 8; nt++) {
                mma16816(acc[0][nt], A0, Bf[nt]);
                mma16816(acc[1][nt], A1, Bf[nt]);
            }
        }
    }

    const int g = lane >> 2, t4 = lane & 3;
    #pragma unroll
    for (int mt = 0; mt < 2; mt++) {
        #pragma unroll
        for (int nt = 0; nt < 8; nt++) {
            const int rowA = m0 + wm + mt * 16 + g;
            const int rowB = rowA + 8;
            const int col  = n0 + wn + nt * 8 + 2 * t4;
            float2 v0 = make_float2(acc[mt][nt][0], acc[mt][nt][1]);
            float2 v1 = make_float2(acc[mt][nt][2], acc[mt][nt][3]);
            *(float2*)(Cf + bz * SD + (size_t)rowA * 1024 + col) = v0;
            *(float2*)(Cf + bz * SD + (size_t)rowB * 1024 + col) = v1;
        }
    }
}

// ---------------------------------------------------------------------------
// Row softmax over 1024, writes attn hi/lo fp16 planes.
// ---------------------------------------------------------------------------
__global__ __launch_bounds__(256)
void softmax_split(const float* __restrict__ s, __half* __restrict__ hi,
                   __half* __restrict__ lo)
{
    const size_t row = blockIdx.x;
    const float4* p = (const float4*)(s + row * 1024);
    const int tid = threadIdx.x;

    float4 v = p[tid];
    float m = fmaxf(fmaxf(v.x, v.y), fmaxf(v.z, v.w));
    #pragma unroll
    for (int o = 16; o > 0; o >>= 1)
        m = fmaxf(m, __shfl_xor_sync(0xffffffffu, m, o));

    __shared__ float red[8];
    __shared__ float fin[2];
    if ((tid & 31) == 0) red[tid >> 5] = m;
    __syncthreads();
    if (tid < 32) {
        float t = (tid < 8) ? red[tid] : -3.4e38f;
        #pragma unroll
        for (int o = 4; o > 0; o >>= 1)
            t = fmaxf(t, __shfl_xor_sync(0xffffffffu, t, o));
        if (tid == 0) fin[0] = t;
    }
    __syncthreads();
    m = fin[0];

    v.x = expf(v.x - m); v.y = expf(v.y - m);
    v.z = expf(v.z - m); v.w = expf(v.w - m);
    float sum = v.x + v.y + v.z + v.w;
    #pragma unroll
    for (int o = 16; o > 0; o >>= 1)
        sum += __shfl_xor_sync(0xffffffffu, sum, o);
    if ((tid & 31) == 0) red[tid >> 5] = sum;
    __syncthreads();
    if (tid < 32) {
        float t = (tid < 8) ? red[tid] : 0.f;
        #pragma unroll
        for (int o = 4; o > 0; o >>= 1)
            t += __shfl_xor_sync(0xffffffffu, t, o);
        if (tid == 0) fin[1] = t;
    }
    __syncthreads();
    const float inv = 1.0f / fin[1];
    v.x *= inv; v.y *= inv; v.z *= inv; v.w *= inv;

    __half h0, h1, h2, h3; float l0, l1, l2, l3;
    fsplit(v.x, h0, l0); fsplit(v.y, h1, l1);
    fsplit(v.z, h2, l2); fsplit(v.w, h3, l3);
    __half2* ph = (__half2*)(hi + row * 1024 + tid * 4);
    __half2* pl = (__half2*)(lo + row * 1024 + tid * 4);
    ph[0] = __halves2half2(h0, h1);
    ph[1] = __halves2half2(h2, h3);
    pl[0] = __halves2half2(__float2half_rn(l0), __float2half_rn(l1));
    pl[1] = __halves2half2(__float2half_rn(l2), __float2half_rn(l3));
}

// ---------------------------------------------------------------------------
// Complex LayerNorm, in place on out = [2, B*S, D].
// ---------------------------------------------------------------------------
__global__ __launch_bounds__(256)
void complex_ln_kernel(float* __restrict__ out,
                       const float* __restrict__ a2,
                       const float* __restrict__ b2)
{
    const size_t row = blockIdx.x;
    float* pr = out + row * 1024;
    float* pi = out + MS + row * 1024;
    const int tid = threadIdx.x;

    float4 zr = ((float4*)pr)[tid];
    float4 zi = ((float4*)pi)[tid];

    float sv[5];
    sv[0] = zr.x + zr.y + zr.z + zr.w;
    sv[1] = zi.x + zi.y + zi.z + zi.w;
    sv[2] = zr.x*zr.x + zr.y*zr.y + zr.z*zr.z + zr.w*zr.w;
    sv[3] = zi.x*zi.x + zi.y*zi.y + zi.z*zi.z + zi.w*zi.w;
    sv[4] = zr.x*zi.x + zr.y*zi.y + zr.z*zi.z + zr.w*zi.w;

    #pragma unroll
    for (int u = 0; u < 5; u++)
        #pragma unroll
        for (int o = 16; o > 0; o >>= 1)
            sv[u] += __shfl_xor_sync(0xffffffffu, sv[u], o);

    __shared__ float red[5][8];
    __shared__ float fin[5];
    if ((tid & 31) == 0) {
        #pragma unroll
        for (int u = 0; u < 5; u++) red[u][tid >> 5] = sv[u];
    }
    __syncthreads();
    if (tid == 0) {
        #pragma unroll
        for (int u = 0; u < 5; u++) {
            float t = 0.f;
            #pragma unroll
            for (int wv = 0; wv < 8; wv++) t += red[u][wv];
            fin[u] = t;
        }
    }
    __syncthreads();

    const float invD = 1.0f / 1024.0f;
    const float mr = fin[0] * invD;
    const float mi = fin[1] * invD;
    const float err = fin[2] * invD - mr * mr;
    const float eii = fin[3] * invD - mi * mi;
    const float eri = fin[4] * invD - mr * mi;
    const float vr = err - eii + 1e-6f;
    const float vi = 2.0f * eri;
    const float rmod = sqrtf(vr * vr + vi * vi);
    const float sre = sqrtf(fmaxf(0.5f * (rmod + vr), 0.f));
    const float sim = copysignf(sqrtf(fmaxf(0.5f * (rmod - vr), 0.f)), vi);
    const float inv = 1.0f / fmaxf(rmod, 1e-30f);

    float4 ga = ((const float4*)a2)[tid];
    float4 gb = ((const float4*)b2)[tid];

    float4 yr, yi;
    {
        float ar = zr.x - mr, ai = zi.x - mi;
        yr.x = (ar * sre + ai * sim) * inv; yi.x = (ai * sre - ar * sim) * inv;
        ar = zr.y - mr; ai = zi.y - mi;
        yr.y = (ar * sre + ai * sim) * inv; yi.y = (ai * sre - ar * sim) * inv;
        ar = zr.z - mr; ai = zi.z - mi;
        yr.z = (ar * sre + ai * sim) * inv; yi.z = (ai * sre - ar * sim) * inv;
        ar = zr.w - mr; ai = zi.w - mi;
        yr.w = (ar * sre + ai * sim) * inv; yi.w = (ai * sre - ar * sim) * inv;
    }
    yr.x = ga.x * yr.x + gb.x; yi.x = ga.x * yi.x;
    yr.y = ga.y * yr.y + gb.y; yi.y = ga.y * yi.y;
    yr.z = ga.z * yr.z + gb.z; yi.z = ga.z * yi.z;
    yr.w = ga.w * yr.w + gb.w; yi.w = ga.w * yi.w;

    ((float4*)pr)[tid] = yr;
    ((float4*)pi)[tid] = yi;
}

// ---------------------------------------------------------------------------
extern "C" void kernel_launch(void* const* d_in, const int* in_sizes, int n_in,
                              void* d_out, int out_size)
{
    const float* a2 = (const float*)d_in[18];
    const float* b2 = (const float*)d_in[19];
    float* out = (float*)d_out;

    __half *xhi, *xlo, *whi, *wlo, *phi, *plo, *thi, *tlo, *ahi, *alo;
    float* scores;
    cudaGetSymbolAddress((void**)&xhi, g_xhi);
    cudaGetSymbolAddress((void**)&xlo, g_xlo);
    cudaGetSymbolAddress((void**)&whi, g_whi);
    cudaGetSymbolAddress((void**)&wlo, g_wlo);
    cudaGetSymbolAddress((void**)&phi, g_phi);
    cudaGetSymbolAddress((void**)&plo, g_plo);
    cudaGetSymbolAddress((void**)&thi, g_thi);
    cudaGetSymbolAddress((void**)&tlo, g_tlo);
    cudaGetSymbolAddress((void**)&ahi, g_ahi);
    cudaGetSymbolAddress((void**)&alo, g_alo);
    cudaGetSymbolAddress((void**)&scores, g_scores);

    cudaFuncSetAttribute(proj_gemm,
        cudaFuncAttributeMaxDynamicSharedMemorySize, GSMEM);
    cudaFuncSetAttribute(scores_gemm,
        cudaFuncAttributeMaxDynamicSharedMemorySize, GSMEM);
    cudaFuncSetAttribute(av_gemm,
        cudaFuncAttributeMaxDynamicSharedMemorySize, GSMEM_AV);

    // 1) split X (6 tensors) and W (6 tensors), one launch each
    {
        Ptr6 xin{}, win{};
        for (int j = 0; j < 6; j++) xin.p[j] = (const float*)d_in[j];
        for (int j = 0; j < 6; j++) win.p[j] = (const float*)d_in[6 + 2*j];
        conv_split6<<<dim3((unsigned)(MS/4/256), 1, 6), 256>>>(
            xin, (__half2*)xhi, (__half2*)xlo, MS/4, MS/4);
        conv_split6<<<dim3((unsigned)(WS/4/256), 1, 6), 256>>>(
            win, (__half2*)whi, (__half2*)wlo, WS/4, WS/4);
    }

    // 2) all six projections in ONE launch (z = j); vr/vi write direct
    {
        Ptr6 bv{};
        for (int j = 0; j < 6; j++) bv.p[j] = (const float*)d_in[7 + 2*j];
        proj_gemm<<<dim3(8, 128, 6), 256, GSMEM>>>(
            xhi, xlo, whi, wlo, bv, phi, plo, thi, tlo);
    }

    // 2b) kr transposes only (hi + lo), one launch
    transpose2<<<dim3(16, 16, 32), dim3(32, 8)>>>(thi, tlo, phi, plo);

    // 3) scores = (qr@krT^T + qi@ki^T)/8: 4 cross (f16 acc) + 2 main (f32)
    {
        SegPtrs sp{};
        sp.a[0] = plo + 0*MS; sp.b[0] = phi + 2*MS;
        sp.a[1] = phi + 0*MS; sp.b[1] = plo + 2*MS;
        sp.a[2] = plo + 1*MS; sp.b[2] = phi + 3*MS;
        sp.a[3] = phi + 1*MS; sp.b[3] = plo + 3*MS;
        sp.a[4] = phi + 0*MS; sp.b[4] = phi + 2*MS;
        sp.a[5] = phi + 1*MS; sp.b[5] = phi + 3*MS;
        scores_gemm<<<dim3(8, 8, BATCH), 256, GSMEM>>>(sp, scores, 0.125f);
    }

    // 4) softmax -> attn hi/lo planes
    softmax_split<<<MTOT, 256>>>(scores, ahi, alo);

    // 5) both attn@V GEMMs in ONE launch, trans-B (v planes untransposed)
    av_gemm<<<dim3(8, 8, 32), 256, GSMEM_AV>>>(ahi, alo, phi, plo, out);

    // 6) complex LayerNorm in place on d_out
    complex_ln_kernel<<<MTOT, 256>>>(out, a2, b2);
}